// round 8
// baseline (speedup 1.0000x reference)
#include <cuda_runtime.h>
#include <cuda_bf16.h>
#include <math.h>
#include <stdint.h>

#define BATCH 4
#define CH    512
#define HW    4096
#define EPS   1e-6f

// ---------------- device scratch (statics; no runtime alloc) ----------------
static __device__ float g_mean[BATCH * 32];
static __device__ float g_rstd[BATCH * 32];
static __device__ __align__(256) __nv_bfloat16 g_xnT_h[(size_t)BATCH * HW * CH];
static __device__ __align__(256) __nv_bfloat16 g_xnT_l[(size_t)BATCH * HW * CH];
static __device__ __align__(256) __nv_bfloat16 g_wqkv_h[3 * CH * CH];
static __device__ __align__(256) __nv_bfloat16 g_wproj_h[CH * CH];
static __device__ __align__(256) __nv_bfloat16 g_wproj_l[CH * CH];
static __device__ __align__(256) __nv_bfloat16 g_qk_h[(size_t)BATCH * HW * 1024];   // q|k [tok][1024]
static __device__ __align__(256) __nv_bfloat16 g_v_h[(size_t)BATCH * CH * HW];      // v [c][tok]
static __device__ __align__(256) float         g_S  [(size_t)BATCH * HW * HW];      // fp32 logits
static __device__ __align__(256) __nv_bfloat16 g_p_h[(size_t)BATCH * HW * HW];      // softmax [i][j]
static __device__ __align__(256) __nv_bfloat16 g_oT_h[(size_t)BATCH * HW * CH];     // O^T [tok][c]
static __device__ __align__(256) __nv_bfloat16 g_oT_l[(size_t)BATCH * HW * CH];

// ---------------- helpers ----------------
__device__ __forceinline__ uint32_t smem_u32(const void* p) {
    uint32_t a;
    asm("{ .reg .u64 t; cvta.to.shared.u64 t, %1; cvt.u32.u64 %0, t; }" : "=r"(a) : "l"(p));
    return a;
}

__device__ __forceinline__ void cp16(uint32_t dst, const void* src) {
    asm volatile("cp.async.cg.shared.global [%0], [%1], 16;" :: "r"(dst), "l"(src));
}
#define CP_COMMIT() asm volatile("cp.async.commit_group;" ::: "memory")
#define CP_WAIT1()  asm volatile("cp.async.wait_group 1;" ::: "memory")
#define CP_WAIT0()  asm volatile("cp.async.wait_group 0;" ::: "memory")

__device__ __forceinline__ void ldm4(uint32_t* r, uint32_t addr) {
    asm volatile("ldmatrix.sync.aligned.m8n8.x4.shared.b16 {%0,%1,%2,%3}, [%4];"
                 : "=r"(r[0]), "=r"(r[1]), "=r"(r[2]), "=r"(r[3]) : "r"(addr));
}

__device__ __forceinline__ void mma16816(float* d, const uint32_t* a, const uint32_t* b) {
    asm volatile(
        "mma.sync.aligned.m16n8k16.row.col.f32.bf16.bf16.f32 "
        "{%0,%1,%2,%3}, {%4,%5,%6,%7}, {%8,%9}, {%0,%1,%2,%3};"
        : "+f"(d[0]), "+f"(d[1]), "+f"(d[2]), "+f"(d[3])
        : "r"(a[0]), "r"(a[1]), "r"(a[2]), "r"(a[3]), "r"(b[0]), "r"(b[1]));
}

__device__ __forceinline__ uint32_t bpack(float a, float b) {
    __nv_bfloat162 t = __floats2bfloat162_rn(a, b);
    return *reinterpret_cast<uint32_t*>(&t);
}
__device__ __forceinline__ float bres(float v) {
    return v - __bfloat162float(__float2bfloat16(v));
}

#define SMEM_BYTES 131072   // 2 stages x up to 4 tiles x 16KB (epilogue needs 68KB)

// ---------------- split-bf16 GEMM: C = A * B^T ----------------
// A: [M][K] hi(/lo if PA) (lda); B: [N][K] hi(/lo if PB) (ldb). Tiles 128x128, K mult of 64.
// passes: ah*bh  (+ ah*bl if PB)  (+ al*bh if PA)
// EPI: 0=QKV  1=S(fp32*alpha)  2=O(bf16 split row-major)  3=PROJ(transposed+bias+resid)
template<int EPI, bool PA, bool PB>
__global__ __launch_bounds__(256, 1) void mma_gemm_kernel(
    const __nv_bfloat16* __restrict__ Ah, const __nv_bfloat16* __restrict__ Al,
    int lda, long long sA,
    const __nv_bfloat16* __restrict__ Bh, const __nv_bfloat16* __restrict__ Bl,
    int ldb, long long sB,
    int K, float alpha, const float* __restrict__ bias,
    float* __restrict__ Cf, long long sCf,
    __nv_bfloat16* __restrict__ Ch, __nv_bfloat16* __restrict__ Cl, long long sC,
    __nv_bfloat16* __restrict__ Vh, long long sV,
    const float* __restrict__ Res, long long sRes)
{
    extern __shared__ char smem[];
    const uint32_t sb = smem_u32(smem);
    const int tid = threadIdx.x, lid = tid & 31, wid = tid >> 5;
    const int bz = blockIdx.z;
    const int m0 = blockIdx.y * 128, n0 = blockIdx.x * 128;

    Ah += (long long)bz * sA;
    if (PA) Al += (long long)bz * sA;
    Bh += (long long)bz * sB;
    if (PB) Bl += (long long)bz * sB;

    const int wm0 = (wid >> 2) * 64, wn0 = (wid & 3) * 32;

    // ---- loader (thread covers seg=tid&7, rows tid>>3 + i*32) ----
    const int l_r0 = tid >> 3, l_seg = tid & 7;
    auto load_stage = [&](int s, int kIter) {
        const uint32_t dst = sb + s * 65536;
        const int k0 = kIter << 6;
        #pragma unroll
        for (int i = 0; i < 4; i++) {
            const int row = l_r0 + i * 32;
            const uint32_t so = row * 128 + ((l_seg ^ (row & 7)) << 4);
            const size_t ga = (size_t)(m0 + row) * lda + k0 + l_seg * 8;
            const size_t gb = (size_t)(n0 + row) * ldb + k0 + l_seg * 8;
            cp16(dst + so,         Ah + ga);
            if (PA) cp16(dst + 16384 + so, Al + ga);
            cp16(dst + 32768 + so, Bh + gb);
            if (PB) cp16(dst + 49152 + so, Bl + gb);
        }
    };

    // ---- fragment lane constants ----
    const int matq = lid >> 3, mr = lid & 7;
    const int a_rb = ((matq & 1) << 3) + mr;   // row-in-16 for A
    const int a_ks = matq >> 1;                // k-16B-seg select for A
    const int b_rb = (((matq >> 1) & 1) << 3) + mr;
    const int b_ks = matq & 1;

    float acc[4][4][4];
    #pragma unroll
    for (int i = 0; i < 4; i++)
        #pragma unroll
        for (int j = 0; j < 4; j++)
            #pragma unroll
            for (int q = 0; q < 4; q++) acc[i][j][q] = 0.f;

    const int niter = K >> 6;
    load_stage(0, 0); CP_COMMIT();
    load_stage(1, 1); CP_COMMIT();
    CP_WAIT1();
    __syncthreads();

    for (int it = 0; it < niter; it++) {
        const uint32_t Ab = sb + (it & 1) * 65536;
        #pragma unroll
        for (int ks = 0; ks < 4; ks++) {
            uint32_t ah[4][4], al[4][4], bh[2][4], bl[2][4];
            #pragma unroll
            for (int mt = 0; mt < 4; mt++) {
                const int r = wm0 + mt * 16 + a_rb;
                const uint32_t ad = Ab + r * 128 + (((ks * 2 + a_ks) ^ (r & 7)) << 4);
                ldm4(ah[mt], ad);
                if (PA) ldm4(al[mt], ad + 16384);
            }
            #pragma unroll
            for (int g = 0; g < 2; g++) {
                const int r = wn0 + g * 16 + b_rb;
                const uint32_t bd = Ab + 32768 + r * 128 + (((ks * 2 + b_ks) ^ (r & 7)) << 4);
                ldm4(bh[g], bd);
                if (PB) ldm4(bl[g], bd + 16384);
            }
            #pragma unroll
            for (int mt = 0; mt < 4; mt++)
                #pragma unroll
                for (int nt = 0; nt < 4; nt++) {
                    const uint32_t* bhp = &bh[nt >> 1][(nt & 1) * 2];
                    mma16816(acc[mt][nt], ah[mt], bhp);
                    if (PB) {
                        const uint32_t* blp = &bl[nt >> 1][(nt & 1) * 2];
                        mma16816(acc[mt][nt], ah[mt], blp);
                    }
                    if (PA) mma16816(acc[mt][nt], al[mt], bhp);
                }
        }
        __syncthreads();
        if (it + 2 < niter) {
            load_stage(it & 1, it + 2); CP_COMMIT(); CP_WAIT1();
        } else {
            CP_COMMIT(); CP_WAIT0();
        }
        __syncthreads();
    }

    // ---- stage fp32 tile to smem (stride 133: conflict-free transpose) ----
    float* cs = reinterpret_cast<float*>(smem);
    #pragma unroll
    for (int mt = 0; mt < 4; mt++) {
        const int r = wm0 + mt * 16 + (lid >> 2);
        #pragma unroll
        for (int nt = 0; nt < 4; nt++) {
            const int c = wn0 + nt * 8 + ((lid & 3) << 1);
            cs[r * 133 + c]           = acc[mt][nt][0];
            cs[r * 133 + c + 1]       = acc[mt][nt][1];
            cs[(r + 8) * 133 + c]     = acc[mt][nt][2];
            cs[(r + 8) * 133 + c + 1] = acc[mt][nt][3];
        }
    }
    __syncthreads();

    // ---- epilogue ----
    if (EPI == 0) {
        if (n0 < 1024) {   // q/k rows: [tok][1024] bf16 hi, +bias
            const float4 bv = *reinterpret_cast<const float4*>(&bias[n0 + lid * 4]);
            __nv_bfloat16* H = Ch + (size_t)bz * sC;
            for (int r = wid; r < 128; r += 8) {
                const float* row = cs + r * 133 + lid * 4;
                const float v0 = row[0] + bv.x, v1 = row[1] + bv.y;
                const float v2 = row[2] + bv.z, v3 = row[3] + bv.w;
                const size_t o = (size_t)(m0 + r) * 1024 + n0 + lid * 4;
                uint2 hi; hi.x = bpack(v0, v1); hi.y = bpack(v2, v3);
                *reinterpret_cast<uint2*>(H + o) = hi;
            }
        } else {           // v: [c][tok] bf16 hi, +bias
            __nv_bfloat16* H = Vh + (size_t)bz * sV;
            for (int c = wid; c < 128; c += 8) {
                const int n = n0 + c;
                const float bvn = bias[n];
                const float v0 = cs[(lid * 4 + 0) * 133 + c] + bvn;
                const float v1 = cs[(lid * 4 + 1) * 133 + c] + bvn;
                const float v2 = cs[(lid * 4 + 2) * 133 + c] + bvn;
                const float v3 = cs[(lid * 4 + 3) * 133 + c] + bvn;
                const size_t o = (size_t)(n - 1024) * HW + m0 + lid * 4;
                uint2 hi; hi.x = bpack(v0, v1); hi.y = bpack(v2, v3);
                *reinterpret_cast<uint2*>(H + o) = hi;
            }
        }
    } else if (EPI == 1) {  // S: fp32 row-major * alpha
        float* C = Cf + (size_t)bz * sCf;
        for (int r = wid; r < 128; r += 8) {
            const float* row = cs + r * 133 + lid * 4;
            float4 v;
            v.x = row[0] * alpha; v.y = row[1] * alpha;
            v.z = row[2] * alpha; v.w = row[3] * alpha;
            *reinterpret_cast<float4*>(C + (size_t)(m0 + r) * HW + n0 + lid * 4) = v;
        }
    } else if (EPI == 2) {  // O^T: [tok][c] split bf16 (hi/lo feed 3-pass PROJ)
        __nv_bfloat16* H = Ch + (size_t)bz * sC;
        __nv_bfloat16* L = Cl + (size_t)bz * sC;
        for (int r = wid; r < 128; r += 8) {
            const float* row = cs + r * 133 + lid * 4;
            const float v0 = row[0], v1 = row[1], v2 = row[2], v3 = row[3];
            const size_t o = (size_t)(m0 + r) * CH + n0 + lid * 4;
            uint2 hi; hi.x = bpack(v0, v1); hi.y = bpack(v2, v3);
            uint2 lo; lo.x = bpack(bres(v0), bres(v1)); lo.y = bpack(bres(v2), bres(v3));
            *reinterpret_cast<uint2*>(H + o) = hi;
            *reinterpret_cast<uint2*>(L + o) = lo;
        }
    } else {                // PROJ: out[c][tok] = tile^T + bias + residual (fp32)
        const float* R = Res + (size_t)bz * sRes;
        float* C = Cf + (size_t)bz * sCf;
        for (int c = wid; c < 128; c += 8) {
            const int n = n0 + c;
            const float bvn = bias[n];
            const size_t o = (size_t)n * HW + m0 + lid * 4;
            const float4 rr = *reinterpret_cast<const float4*>(R + o);
            float4 v;
            v.x = cs[(lid * 4 + 0) * 133 + c] + bvn + rr.x;
            v.y = cs[(lid * 4 + 1) * 133 + c] + bvn + rr.y;
            v.z = cs[(lid * 4 + 2) * 133 + c] + bvn + rr.z;
            v.w = cs[(lid * 4 + 3) * 133 + c] + bvn + rr.w;
            *reinterpret_cast<float4*>(C + o) = v;
        }
    }
}

// ---------------- GroupNorm stats ----------------
__global__ __launch_bounds__(256) void gn_stats_kernel(const float* __restrict__ x)
{
    const int bg = blockIdx.x;
    const size_t base = (size_t)bg * 16 * HW;
    const int n = 16 * HW;
    float s = 0.f, ss = 0.f;
    for (int i = threadIdx.x; i < n; i += 256) {
        float v = x[base + i];
        s += v; ss += v * v;
    }
    #pragma unroll
    for (int o = 16; o > 0; o >>= 1) {
        s  += __shfl_xor_sync(0xffffffffu, s,  o);
        ss += __shfl_xor_sync(0xffffffffu, ss, o);
    }
    __shared__ float sh[16];
    const int w = threadIdx.x >> 5, l = threadIdx.x & 31;
    if (l == 0) { sh[w] = s; sh[8 + w] = ss; }
    __syncthreads();
    if (threadIdx.x == 0) {
        float S = 0.f, SS = 0.f;
        #pragma unroll
        for (int i = 0; i < 8; i++) { S += sh[i]; SS += sh[8 + i]; }
        float mean = S / (float)n;
        float var  = SS / (float)n - mean * mean;
        g_mean[bg] = mean;
        g_rstd[bg] = rsqrtf(var + EPS);
    }
}

// ---------------- normalize + transpose + bf16 split ----------------
__global__ __launch_bounds__(256) void normT_kernel(
    const float* __restrict__ x, const float* __restrict__ gamma,
    const float* __restrict__ beta,
    __nv_bfloat16* __restrict__ th, __nv_bfloat16* __restrict__ tl)
{
    __shared__ float tile[64][65];
    const int b = blockIdx.z, c0 = blockIdx.y * 64, t0 = blockIdx.x * 64;
    const int lane = threadIdx.x & 63, r0 = threadIdx.x >> 6;
    #pragma unroll
    for (int r = r0; r < 64; r += 4) {
        const int c = c0 + r;
        const int gr = b * 32 + (c >> 4);
        float v = x[((size_t)b * CH + c) * HW + t0 + lane];
        tile[r][lane] = (v - g_mean[gr]) * g_rstd[gr] * gamma[c] + beta[c];
    }
    __syncthreads();
    #pragma unroll
    for (int r = r0; r < 64; r += 4) {
        const float v = tile[lane][r];
        const size_t o = ((size_t)b * HW + t0 + r) * CH + c0 + lane;
        __nv_bfloat16 hv = __float2bfloat16(v);
        th[o] = hv;
        tl[o] = __float2bfloat16(v - __bfloat162float(hv));
    }
}

// ---------------- weight fp32 -> hi(/lo) split ----------------
__global__ void wsplit_kernel(const float* __restrict__ in,
                              __nv_bfloat16* __restrict__ h,
                              __nv_bfloat16* __restrict__ l, int n)
{
    int i = blockIdx.x * 256 + threadIdx.x;
    if (i < n) {
        float v = in[i];
        __nv_bfloat16 hv = __float2bfloat16(v);
        h[i] = hv;
        if (l) l[i] = __float2bfloat16(v - __bfloat162float(hv));
    }
}

// ---------------- softmax (fp32 in, bf16 hi out) ----------------
__global__ __launch_bounds__(256) void softmax_kernel(
    const float* __restrict__ S, __nv_bfloat16* __restrict__ ph)
{
    const size_t base = (size_t)blockIdx.x * HW;
    const float* p = S + base;

    float v[16];
    float mx = -INFINITY;
    #pragma unroll
    for (int i = 0; i < 16; i++) {
        v[i] = p[threadIdx.x + i * 256];
        mx = fmaxf(mx, v[i]);
    }
    #pragma unroll
    for (int o = 16; o > 0; o >>= 1)
        mx = fmaxf(mx, __shfl_xor_sync(0xffffffffu, mx, o));

    __shared__ float sh[10];
    const int w = threadIdx.x >> 5, l = threadIdx.x & 31;
    if (l == 0) sh[w] = mx;
    __syncthreads();
    if (threadIdx.x == 0) {
        float m = sh[0];
        #pragma unroll
        for (int i = 1; i < 8; i++) m = fmaxf(m, sh[i]);
        sh[8] = m;
    }
    __syncthreads();
    mx = sh[8];

    float sum = 0.f;
    #pragma unroll
    for (int i = 0; i < 16; i++) { v[i] = __expf(v[i] - mx); sum += v[i]; }
    #pragma unroll
    for (int o = 16; o > 0; o >>= 1)
        sum += __shfl_xor_sync(0xffffffffu, sum, o);
    if (l == 0) sh[w] = sum;
    __syncthreads();
    if (threadIdx.x == 0) {
        float s = 0.f;
        #pragma unroll
        for (int i = 0; i < 8; i++) s += sh[i];
        sh[9] = 1.f / s;
    }
    __syncthreads();
    const float inv = sh[9];

    #pragma unroll
    for (int i = 0; i < 8; i++) {
        const size_t o = base + threadIdx.x * 2 + i * 512;
        // note: layout change for vector store: recompute pairs from v[]
        // v[] was loaded strided by 256; store must match load addressing:
        ;
    }
    #pragma unroll
    for (int i = 0; i < 16; i++) {
        const size_t o = base + threadIdx.x + i * 256;
        ph[o] = __float2bfloat16(v[i] * inv);
    }
}

// ---------------- launch ----------------
extern "C" void kernel_launch(void* const* d_in, const int* in_sizes, int n_in,
                              void* d_out, int out_size)
{
    const float* x      = (const float*)d_in[0];
    const float* gamma  = (const float*)d_in[1];
    const float* beta   = (const float*)d_in[2];
    const float* w_qkv  = (const float*)d_in[3];
    const float* b_qkv  = (const float*)d_in[4];
    const float* w_proj = (const float*)d_in[5];
    const float* b_proj = (const float*)d_in[6];
    float* out = (float*)d_out;

    __nv_bfloat16 *xnT_h, *xnT_l, *wqkv_h, *wproj_h, *wproj_l;
    __nv_bfloat16 *qk_h, *v_h, *p_h, *oT_h, *oT_l;
    float* S;
    cudaGetSymbolAddress((void**)&xnT_h, g_xnT_h);
    cudaGetSymbolAddress((void**)&xnT_l, g_xnT_l);
    cudaGetSymbolAddress((void**)&wqkv_h, g_wqkv_h);
    cudaGetSymbolAddress((void**)&wproj_h, g_wproj_h);
    cudaGetSymbolAddress((void**)&wproj_l, g_wproj_l);
    cudaGetSymbolAddress((void**)&qk_h, g_qk_h);
    cudaGetSymbolAddress((void**)&v_h, g_v_h);
    cudaGetSymbolAddress((void**)&S, g_S);
    cudaGetSymbolAddress((void**)&p_h, g_p_h);
    cudaGetSymbolAddress((void**)&oT_h, g_oT_h);
    cudaGetSymbolAddress((void**)&oT_l, g_oT_l);

    cudaFuncSetAttribute((const void*)mma_gemm_kernel<0, true, false>,  cudaFuncAttributeMaxDynamicSharedMemorySize, SMEM_BYTES);
    cudaFuncSetAttribute((const void*)mma_gemm_kernel<1, false, false>, cudaFuncAttributeMaxDynamicSharedMemorySize, SMEM_BYTES);
    cudaFuncSetAttribute((const void*)mma_gemm_kernel<2, false, false>, cudaFuncAttributeMaxDynamicSharedMemorySize, SMEM_BYTES);
    cudaFuncSetAttribute((const void*)mma_gemm_kernel<3, true, true>,   cudaFuncAttributeMaxDynamicSharedMemorySize, SMEM_BYTES);

    const long long sTok = (long long)HW * CH;
    const long long sQK  = (long long)HW * 1024;
    const long long sS   = (long long)HW * HW;
    const float scale2 = 1.f / sqrtf((float)CH);

    // 1) weight splits (w_qkv hi only; w_proj hi/lo)
    wsplit_kernel<<<(3 * CH * CH + 255) / 256, 256>>>(w_qkv, wqkv_h, nullptr, 3 * CH * CH);
    wsplit_kernel<<<(CH * CH + 255) / 256, 256>>>(w_proj, wproj_h, wproj_l, CH * CH);

    // 2) GroupNorm stats + normalize/transpose/split
    gn_stats_kernel<<<BATCH * 32, 256>>>(x);
    normT_kernel<<<dim3(HW / 64, CH / 64, BATCH), 256>>>(x, gamma, beta, xnT_h, xnT_l);

    // 3) QKV (2-pass: (xh+xl)*wh): C[tok][oc] = xnT . w_qkv^T  (M=4096, N=1536, K=512)
    mma_gemm_kernel<0, true, false><<<dim3(12, 32, BATCH), 256, SMEM_BYTES>>>(
        xnT_h, xnT_l, CH, sTok, wqkv_h, nullptr, CH, 0,
        CH, 1.f, b_qkv,
        nullptr, 0, qk_h, nullptr, sQK, v_h, sTok, nullptr, 0);

    // 4) S (1-pass): S[i][j] = qh . kh^T * scale  (M=N=4096, K=512)
    mma_gemm_kernel<1, false, false><<<dim3(32, 32, BATCH), 256, SMEM_BYTES>>>(
        qk_h, nullptr, 1024, sQK, qk_h + CH, nullptr, 1024, sQK,
        CH, scale2, nullptr,
        S, sS, nullptr, nullptr, 0, nullptr, 0, nullptr, 0);

    // 5) softmax rows -> p hi
    softmax_kernel<<<BATCH * HW, 256>>>(S, p_h);

    // 6) O (1-pass): O^T[tok][c] = ph . vh^T  (M=4096, N=512, K=4096)
    mma_gemm_kernel<2, false, false><<<dim3(4, 32, BATCH), 256, SMEM_BYTES>>>(
        p_h, nullptr, HW, sS, v_h, nullptr, HW, sTok,
        HW, 1.f, nullptr,
        nullptr, 0, oT_h, oT_l, sTok, nullptr, 0, nullptr, 0);

    // 7) PROJ (3-pass): out[c][tok] = oT . w_proj^T + b_proj + x  (M=4096, N=512, K=512)
    mma_gemm_kernel<3, true, true><<<dim3(4, 32, BATCH), 256, SMEM_BYTES>>>(
        oT_h, oT_l, CH, sTok, wproj_h, wproj_l, CH, 0,
        CH, 1.f, b_proj,
        out, sTok, nullptr, nullptr, 0, nullptr, 0, x, sTok);
}

// round 12
// speedup vs baseline: 1.7714x; 1.7714x over previous
#include <cuda_runtime.h>
#include <cuda_bf16.h>
#include <math.h>
#include <stdint.h>

#define BATCH 4
#define CH    512
#define HW    4096
#define EPS   1e-6f

// ---------------- device scratch (statics; no runtime alloc) ----------------
static __device__ float g_mean[BATCH * 32];
static __device__ float g_rstd[BATCH * 32];
static __device__ __align__(256) __nv_bfloat16 g_xnT_h[(size_t)BATCH * HW * CH];
static __device__ __align__(256) __nv_bfloat16 g_xnT_l[(size_t)BATCH * HW * CH];
static __device__ __align__(256) __nv_bfloat16 g_wqkv_h[3 * CH * CH];
static __device__ __align__(256) __nv_bfloat16 g_wproj_h[CH * CH];
static __device__ __align__(256) __nv_bfloat16 g_wproj_l[CH * CH];
static __device__ __align__(256) __nv_bfloat16 g_qk_h[(size_t)BATCH * HW * 1024];   // q|k [tok][1024]
static __device__ __align__(256) __nv_bfloat16 g_v_h[(size_t)BATCH * CH * HW];      // v [c][tok]
static __device__ __align__(256) float         g_S  [(size_t)BATCH * HW * HW];      // fp32 logits
static __device__ __align__(256) __nv_bfloat16 g_p_h[(size_t)BATCH * HW * HW];      // softmax [i][j]
static __device__ __align__(256) __nv_bfloat16 g_oT_h[(size_t)BATCH * HW * CH];     // O^T [tok][c]
static __device__ __align__(256) __nv_bfloat16 g_oT_l[(size_t)BATCH * HW * CH];

// ---------------- helpers ----------------
__device__ __forceinline__ uint32_t smem_u32(const void* p) {
    uint32_t a;
    asm("{ .reg .u64 t; cvta.to.shared.u64 t, %1; cvt.u32.u64 %0, t; }" : "=r"(a) : "l"(p));
    return a;
}

__device__ __forceinline__ void cp16(uint32_t dst, const void* src) {
    asm volatile("cp.async.cg.shared.global [%0], [%1], 16;" :: "r"(dst), "l"(src));
}
#define CP_COMMIT() asm volatile("cp.async.commit_group;" ::: "memory")
#define CP_WAIT1()  asm volatile("cp.async.wait_group 1;" ::: "memory")
#define CP_WAIT0()  asm volatile("cp.async.wait_group 0;" ::: "memory")

__device__ __forceinline__ void ldm4(uint32_t* r, uint32_t addr) {
    asm volatile("ldmatrix.sync.aligned.m8n8.x4.shared.b16 {%0,%1,%2,%3}, [%4];"
                 : "=r"(r[0]), "=r"(r[1]), "=r"(r[2]), "=r"(r[3]) : "r"(addr));
}

__device__ __forceinline__ void mma16816(float* d, const uint32_t* a, const uint32_t* b) {
    asm volatile(
        "mma.sync.aligned.m16n8k16.row.col.f32.bf16.bf16.f32 "
        "{%0,%1,%2,%3}, {%4,%5,%6,%7}, {%8,%9}, {%0,%1,%2,%3};"
        : "+f"(d[0]), "+f"(d[1]), "+f"(d[2]), "+f"(d[3])
        : "r"(a[0]), "r"(a[1]), "r"(a[2]), "r"(a[3]), "r"(b[0]), "r"(b[1]));
}

__device__ __forceinline__ uint32_t bpack(float a, float b) {
    __nv_bfloat162 t = __floats2bfloat162_rn(a, b);
    return *reinterpret_cast<uint32_t*>(&t);
}
__device__ __forceinline__ float bres(float v) {
    return v - __bfloat162float(__float2bfloat16(v));
}

// ---------------- split-bf16 GEMM: C = A * B^T ----------------
// A: [M][K] hi(/lo if PA) (lda); B: [N][K] hi(/lo if PB) (ldb). Tiles 128x128, K mult of 64.
// passes: ah*bh  (+ ah*bl if PB)  (+ al*bh if PA)
// EPI: 0=QKV  1=S(fp32*alpha, direct reg store)  2=O(split bf16 row-major)  3=PROJ(transposed+bias+resid)
// smem/stage = (1+PA+1+PB)*16KB; 2 stages. Epilogue (EPI!=1) stages 64 rows at a time (34KB).
template<int EPI, bool PA, bool PB>
__global__ __launch_bounds__(256, (PA && PB) ? 1 : 2) void mma_gemm_kernel(
    const __nv_bfloat16* __restrict__ Ah, const __nv_bfloat16* __restrict__ Al,
    int lda, long long sA,
    const __nv_bfloat16* __restrict__ Bh, const __nv_bfloat16* __restrict__ Bl,
    int ldb, long long sB,
    int K, float alpha, const float* __restrict__ bias,
    float* __restrict__ Cf, long long sCf,
    __nv_bfloat16* __restrict__ Ch, __nv_bfloat16* __restrict__ Cl, long long sC,
    __nv_bfloat16* __restrict__ Vh, long long sV,
    const float* __restrict__ Res, long long sRes)
{
    constexpr int NA = 1 + (PA ? 1 : 0);
    constexpr int NB = 1 + (PB ? 1 : 0);
    constexpr uint32_t STAGE = (NA + NB) * 16384;

    extern __shared__ char smem[];
    const uint32_t sb = smem_u32(smem);
    const int tid = threadIdx.x, lid = tid & 31, wid = tid >> 5;
    const int bz = blockIdx.z;
    const int m0 = blockIdx.y * 128, n0 = blockIdx.x * 128;

    Ah += (long long)bz * sA;
    if (PA) Al += (long long)bz * sA;
    Bh += (long long)bz * sB;
    if (PB) Bl += (long long)bz * sB;

    const int wm0 = (wid >> 2) * 64, wn0 = (wid & 3) * 32;

    // ---- loader (thread covers seg=tid&7, rows tid>>3 + i*32) ----
    const int l_r0 = tid >> 3, l_seg = tid & 7;
    auto load_stage = [&](int s, int kIter) {
        const uint32_t dst = sb + s * STAGE;
        const int k0 = kIter << 6;
        #pragma unroll
        for (int i = 0; i < 4; i++) {
            const int row = l_r0 + i * 32;
            const uint32_t so = row * 128 + ((l_seg ^ (row & 7)) << 4);
            const size_t ga = (size_t)(m0 + row) * lda + k0 + l_seg * 8;
            const size_t gb = (size_t)(n0 + row) * ldb + k0 + l_seg * 8;
            cp16(dst + so, Ah + ga);
            if (PA) cp16(dst + 16384 + so, Al + ga);
            cp16(dst + NA * 16384 + so, Bh + gb);
            if (PB) cp16(dst + NA * 16384 + 16384 + so, Bl + gb);
        }
    };

    // ---- fragment lane constants ----
    const int matq = lid >> 3, mr = lid & 7;
    const int a_rb = ((matq & 1) << 3) + mr;
    const int a_ks = matq >> 1;
    const int b_rb = (((matq >> 1) & 1) << 3) + mr;
    const int b_ks = matq & 1;

    float acc[4][4][4];
    #pragma unroll
    for (int i = 0; i < 4; i++)
        #pragma unroll
        for (int j = 0; j < 4; j++)
            #pragma unroll
            for (int q = 0; q < 4; q++) acc[i][j][q] = 0.f;

    const int niter = K >> 6;
    load_stage(0, 0); CP_COMMIT();
    load_stage(1, 1); CP_COMMIT();
    CP_WAIT1();
    __syncthreads();

    for (int it = 0; it < niter; it++) {
        const uint32_t Ab = sb + (it & 1) * STAGE;
        #pragma unroll
        for (int ks = 0; ks < 4; ks++) {
            uint32_t ah[4][4], al[4][4], bh[2][4], bl[2][4];
            #pragma unroll
            for (int mt = 0; mt < 4; mt++) {
                const int r = wm0 + mt * 16 + a_rb;
                const uint32_t ad = Ab + r * 128 + (((ks * 2 + a_ks) ^ (r & 7)) << 4);
                ldm4(ah[mt], ad);
                if (PA) ldm4(al[mt], ad + 16384);
            }
            #pragma unroll
            for (int g = 0; g < 2; g++) {
                const int r = wn0 + g * 16 + b_rb;
                const uint32_t bd = Ab + NA * 16384 + r * 128 + (((ks * 2 + b_ks) ^ (r & 7)) << 4);
                ldm4(bh[g], bd);
                if (PB) ldm4(bl[g], bd + 16384);
            }
            #pragma unroll
            for (int mt = 0; mt < 4; mt++)
                #pragma unroll
                for (int nt = 0; nt < 4; nt++) {
                    const uint32_t* bhp = &bh[nt >> 1][(nt & 1) * 2];
                    mma16816(acc[mt][nt], ah[mt], bhp);
                    if (PB) {
                        const uint32_t* blp = &bl[nt >> 1][(nt & 1) * 2];
                        mma16816(acc[mt][nt], ah[mt], blp);
                    }
                    if (PA) mma16816(acc[mt][nt], al[mt], bhp);
                }
        }
        __syncthreads();
        if (it + 2 < niter) {
            load_stage(it & 1, it + 2); CP_COMMIT(); CP_WAIT1();
        } else {
            CP_COMMIT(); CP_WAIT0();
        }
        __syncthreads();
    }

    // ---------------- epilogue ----------------
    if (EPI == 1) {
        // S: direct register store, fp32 * alpha, row-major [i][j]
        float* C = Cf + (size_t)bz * sCf;
        #pragma unroll
        for (int mt = 0; mt < 4; mt++) {
            const int rg = m0 + wm0 + mt * 16 + (lid >> 2);
            #pragma unroll
            for (int nt = 0; nt < 4; nt++) {
                const int c = n0 + wn0 + nt * 8 + ((lid & 3) << 1);
                float2 v0 = make_float2(acc[mt][nt][0] * alpha, acc[mt][nt][1] * alpha);
                float2 v1 = make_float2(acc[mt][nt][2] * alpha, acc[mt][nt][3] * alpha);
                *reinterpret_cast<float2*>(C + (size_t)rg * HW + c)       = v0;
                *reinterpret_cast<float2*>(C + (size_t)(rg + 8) * HW + c) = v1;
            }
        }
        return;
    }

    // staged epilogue in 2 halves of 64 rows (cs = 64x133 floats = 34KB, fits all variants)
    float* cs = reinterpret_cast<float*>(smem);
    #pragma unroll
    for (int h = 0; h < 2; h++) {
        __syncthreads();
        if ((wid >> 2) == h) {
            #pragma unroll
            for (int mt = 0; mt < 4; mt++) {
                const int rl = mt * 16 + (lid >> 2);
                #pragma unroll
                for (int nt = 0; nt < 4; nt++) {
                    const int c = wn0 + nt * 8 + ((lid & 3) << 1);
                    cs[rl * 133 + c]           = acc[mt][nt][0];
                    cs[rl * 133 + c + 1]       = acc[mt][nt][1];
                    cs[(rl + 8) * 133 + c]     = acc[mt][nt][2];
                    cs[(rl + 8) * 133 + c + 1] = acc[mt][nt][3];
                }
            }
        }
        __syncthreads();
        const int mh = m0 + h * 64;

        if (EPI == 0) {
            if (n0 < 1024) {   // q/k: [tok][1024] bf16 hi, +bias
                const float4 bv = *reinterpret_cast<const float4*>(&bias[n0 + lid * 4]);
                __nv_bfloat16* H = Ch + (size_t)bz * sC;
                for (int rl = wid; rl < 64; rl += 8) {
                    const float* row = cs + rl * 133 + lid * 4;
                    const float v0 = row[0] + bv.x, v1 = row[1] + bv.y;
                    const float v2 = row[2] + bv.z, v3 = row[3] + bv.w;
                    const size_t o = (size_t)(mh + rl) * 1024 + n0 + lid * 4;
                    uint2 hi; hi.x = bpack(v0, v1); hi.y = bpack(v2, v3);
                    *reinterpret_cast<uint2*>(H + o) = hi;
                }
            } else {           // v: [c][tok] bf16 hi, +bias (transposed)
                __nv_bfloat16* H = Vh + (size_t)bz * sV;
                for (int c = wid; c < 128; c += 8) {
                    const int n = n0 + c;
                    const float bvn = bias[n];
                    const float v0 = cs[(lid * 2 + 0) * 133 + c] + bvn;
                    const float v1 = cs[(lid * 2 + 1) * 133 + c] + bvn;
                    const size_t o = (size_t)(n - 1024) * HW + mh + lid * 2;
                    *reinterpret_cast<uint32_t*>(H + o) = bpack(v0, v1);
                }
            }
        } else if (EPI == 2) {  // O^T: [tok][c] split bf16
            __nv_bfloat16* H = Ch + (size_t)bz * sC;
            __nv_bfloat16* L = Cl + (size_t)bz * sC;
            for (int rl = wid; rl < 64; rl += 8) {
                const float* row = cs + rl * 133 + lid * 4;
                const float v0 = row[0], v1 = row[1], v2 = row[2], v3 = row[3];
                const size_t o = (size_t)(mh + rl) * CH + n0 + lid * 4;
                uint2 hi; hi.x = bpack(v0, v1); hi.y = bpack(v2, v3);
                uint2 lo; lo.x = bpack(bres(v0), bres(v1)); lo.y = bpack(bres(v2), bres(v3));
                *reinterpret_cast<uint2*>(H + o) = hi;
                *reinterpret_cast<uint2*>(L + o) = lo;
            }
        } else {                // PROJ: out[c][tok] = tile^T + bias + residual (fp32)
            const float* R = Res + (size_t)bz * sRes;
            float* C = Cf + (size_t)bz * sCf;
            for (int c = wid; c < 128; c += 8) {
                const int n = n0 + c;
                const float bvn = bias[n];
                const size_t o = (size_t)n * HW + mh + lid * 2;
                const float2 rr = *reinterpret_cast<const float2*>(R + o);
                float2 v;
                v.x = cs[(lid * 2 + 0) * 133 + c] + bvn + rr.x;
                v.y = cs[(lid * 2 + 1) * 133 + c] + bvn + rr.y;
                *reinterpret_cast<float2*>(C + o) = v;
            }
        }
    }
}

// ---------------- GroupNorm stats ----------------
__global__ __launch_bounds__(256) void gn_stats_kernel(const float* __restrict__ x)
{
    const int bg = blockIdx.x;
    const size_t base = (size_t)bg * 16 * HW;
    const int n = 16 * HW;
    float s = 0.f, ss = 0.f;
    for (int i = threadIdx.x; i < n; i += 256) {
        float v = x[base + i];
        s += v; ss += v * v;
    }
    #pragma unroll
    for (int o = 16; o > 0; o >>= 1) {
        s  += __shfl_xor_sync(0xffffffffu, s,  o);
        ss += __shfl_xor_sync(0xffffffffu, ss, o);
    }
    __shared__ float sh[16];
    const int w = threadIdx.x >> 5, l = threadIdx.x & 31;
    if (l == 0) { sh[w] = s; sh[8 + w] = ss; }
    __syncthreads();
    if (threadIdx.x == 0) {
        float S = 0.f, SS = 0.f;
        #pragma unroll
        for (int i = 0; i < 8; i++) { S += sh[i]; SS += sh[8 + i]; }
        float mean = S / (float)n;
        float var  = SS / (float)n - mean * mean;
        g_mean[bg] = mean;
        g_rstd[bg] = rsqrtf(var + EPS);
    }
}

// ---------------- normalize + transpose + bf16 split ----------------
__global__ __launch_bounds__(256) void normT_kernel(
    const float* __restrict__ x, const float* __restrict__ gamma,
    const float* __restrict__ beta,
    __nv_bfloat16* __restrict__ th, __nv_bfloat16* __restrict__ tl)
{
    __shared__ float tile[64][65];
    const int b = blockIdx.z, c0 = blockIdx.y * 64, t0 = blockIdx.x * 64;
    const int lane = threadIdx.x & 63, r0 = threadIdx.x >> 6;
    #pragma unroll
    for (int r = r0; r < 64; r += 4) {
        const int c = c0 + r;
        const int gr = b * 32 + (c >> 4);
        float v = x[((size_t)b * CH + c) * HW + t0 + lane];
        tile[r][lane] = (v - g_mean[gr]) * g_rstd[gr] * gamma[c] + beta[c];
    }
    __syncthreads();
    #pragma unroll
    for (int r = r0; r < 64; r += 4) {
        const float v = tile[lane][r];
        const size_t o = ((size_t)b * HW + t0 + r) * CH + c0 + lane;
        __nv_bfloat16 hv = __float2bfloat16(v);
        th[o] = hv;
        tl[o] = __float2bfloat16(v - __bfloat162float(hv));
    }
}

// ---------------- weight fp32 -> hi(/lo) split ----------------
__global__ void wsplit_kernel(const float* __restrict__ in,
                              __nv_bfloat16* __restrict__ h,
                              __nv_bfloat16* __restrict__ l, int n)
{
    int i = blockIdx.x * 256 + threadIdx.x;
    if (i < n) {
        float v = in[i];
        __nv_bfloat16 hv = __float2bfloat16(v);
        h[i] = hv;
        if (l) l[i] = __float2bfloat16(v - __bfloat162float(hv));
    }
}

// ---------------- softmax (fp32 in, bf16 hi out) ----------------
__global__ __launch_bounds__(256) void softmax_kernel(
    const float* __restrict__ S, __nv_bfloat16* __restrict__ ph)
{
    const size_t base = (size_t)blockIdx.x * HW;
    const float* p = S + base;

    float v[16];
    float mx = -INFINITY;
    #pragma unroll
    for (int i = 0; i < 16; i++) {
        v[i] = p[threadIdx.x + i * 256];
        mx = fmaxf(mx, v[i]);
    }
    #pragma unroll
    for (int o = 16; o > 0; o >>= 1)
        mx = fmaxf(mx, __shfl_xor_sync(0xffffffffu, mx, o));

    __shared__ float sh[10];
    const int w = threadIdx.x >> 5, l = threadIdx.x & 31;
    if (l == 0) sh[w] = mx;
    __syncthreads();
    if (threadIdx.x == 0) {
        float m = sh[0];
        #pragma unroll
        for (int i = 1; i < 8; i++) m = fmaxf(m, sh[i]);
        sh[8] = m;
    }
    __syncthreads();
    mx = sh[8];

    float sum = 0.f;
    #pragma unroll
    for (int i = 0; i < 16; i++) { v[i] = __expf(v[i] - mx); sum += v[i]; }
    #pragma unroll
    for (int o = 16; o > 0; o >>= 1)
        sum += __shfl_xor_sync(0xffffffffu, sum, o);
    if (l == 0) sh[w] = sum;
    __syncthreads();
    if (threadIdx.x == 0) {
        float s = 0.f;
        #pragma unroll
        for (int i = 0; i < 8; i++) s += sh[i];
        sh[9] = 1.f / s;
    }
    __syncthreads();
    const float inv = sh[9];

    #pragma unroll
    for (int i = 0; i < 16; i++) {
        const size_t o = base + threadIdx.x + i * 256;
        ph[o] = __float2bfloat16(v[i] * inv);
    }
}

// ---------------- launch ----------------
extern "C" void kernel_launch(void* const* d_in, const int* in_sizes, int n_in,
                              void* d_out, int out_size)
{
    const float* x      = (const float*)d_in[0];
    const float* gamma  = (const float*)d_in[1];
    const float* beta   = (const float*)d_in[2];
    const float* w_qkv  = (const float*)d_in[3];
    const float* b_qkv  = (const float*)d_in[4];
    const float* w_proj = (const float*)d_in[5];
    const float* b_proj = (const float*)d_in[6];
    float* out = (float*)d_out;

    __nv_bfloat16 *xnT_h, *xnT_l, *wqkv_h, *wproj_h, *wproj_l;
    __nv_bfloat16 *qk_h, *v_h, *p_h, *oT_h, *oT_l;
    float* S;
    cudaGetSymbolAddress((void**)&xnT_h, g_xnT_h);
    cudaGetSymbolAddress((void**)&xnT_l, g_xnT_l);
    cudaGetSymbolAddress((void**)&wqkv_h, g_wqkv_h);
    cudaGetSymbolAddress((void**)&wproj_h, g_wproj_h);
    cudaGetSymbolAddress((void**)&wproj_l, g_wproj_l);
    cudaGetSymbolAddress((void**)&qk_h, g_qk_h);
    cudaGetSymbolAddress((void**)&v_h, g_v_h);
    cudaGetSymbolAddress((void**)&S, g_S);
    cudaGetSymbolAddress((void**)&p_h, g_p_h);
    cudaGetSymbolAddress((void**)&oT_h, g_oT_h);
    cudaGetSymbolAddress((void**)&oT_l, g_oT_l);

    const int SM_QKV  = 3 * 16384 * 2;   // 96KB  (2 CTAs/SM)
    const int SM_SO   = 2 * 16384 * 2;   // 64KB  (2 CTAs/SM)
    const int SM_PROJ = 4 * 16384 * 2;   // 128KB (1 CTA/SM)

    cudaFuncSetAttribute((const void*)mma_gemm_kernel<0, true, false>,  cudaFuncAttributeMaxDynamicSharedMemorySize, SM_QKV);
    cudaFuncSetAttribute((const void*)mma_gemm_kernel<1, false, false>, cudaFuncAttributeMaxDynamicSharedMemorySize, SM_SO);
    cudaFuncSetAttribute((const void*)mma_gemm_kernel<2, false, false>, cudaFuncAttributeMaxDynamicSharedMemorySize, SM_SO);
    cudaFuncSetAttribute((const void*)mma_gemm_kernel<3, true, true>,   cudaFuncAttributeMaxDynamicSharedMemorySize, SM_PROJ);

    const long long sTok = (long long)HW * CH;
    const long long sQK  = (long long)HW * 1024;
    const long long sS   = (long long)HW * HW;
    const float scale2 = 1.f / sqrtf((float)CH);

    // 1) weight splits (w_qkv hi only; w_proj hi/lo)
    wsplit_kernel<<<(3 * CH * CH + 255) / 256, 256>>>(w_qkv, wqkv_h, nullptr, 3 * CH * CH);
    wsplit_kernel<<<(CH * CH + 255) / 256, 256>>>(w_proj, wproj_h, wproj_l, CH * CH);

    // 2) GroupNorm stats + normalize/transpose/split
    gn_stats_kernel<<<BATCH * 32, 256>>>(x);
    normT_kernel<<<dim3(HW / 64, CH / 64, BATCH), 256>>>(x, gamma, beta, xnT_h, xnT_l);

    // 3) QKV (2-pass: (xh+xl)*wh): C[tok][oc] = xnT . w_qkv^T  (M=4096, N=1536, K=512)
    mma_gemm_kernel<0, true, false><<<dim3(12, 32, BATCH), 256, SM_QKV>>>(
        xnT_h, xnT_l, CH, sTok, wqkv_h, nullptr, CH, 0,
        CH, 1.f, b_qkv,
        nullptr, 0, qk_h, nullptr, sQK, v_h, sTok, nullptr, 0);

    // 4) S (1-pass): S[i][j] = qh . kh^T * scale  (M=N=4096, K=512)
    mma_gemm_kernel<1, false, false><<<dim3(32, 32, BATCH), 256, SM_SO>>>(
        qk_h, nullptr, 1024, sQK, qk_h + CH, nullptr, 1024, sQK,
        CH, scale2, nullptr,
        S, sS, nullptr, nullptr, 0, nullptr, 0, nullptr, 0);

    // 5) softmax rows -> p hi
    softmax_kernel<<<BATCH * HW, 256>>>(S, p_h);

    // 6) O (1-pass): O^T[tok][c] = ph . vh^T  (M=4096, N=512, K=4096)
    mma_gemm_kernel<2, false, false><<<dim3(4, 32, BATCH), 256, SM_SO>>>(
        p_h, nullptr, HW, sS, v_h, nullptr, HW, sTok,
        HW, 1.f, nullptr,
        nullptr, 0, oT_h, oT_l, sTok, nullptr, 0, nullptr, 0);

    // 7) PROJ (3-pass): out[c][tok] = oT . w_proj^T + b_proj + x  (M=4096, N=512, K=512)
    mma_gemm_kernel<3, true, true><<<dim3(4, 32, BATCH), 256, SM_PROJ>>>(
        oT_h, oT_l, CH, sTok, wproj_h, wproj_l, CH, 0,
        CH, 1.f, b_proj,
        out, sTok, nullptr, nullptr, 0, nullptr, 0, x, sTok);
}

// round 14
// speedup vs baseline: 1.9366x; 1.0932x over previous
#include <cuda_runtime.h>
#include <cuda_bf16.h>
#include <math.h>
#include <stdint.h>

#define BATCH 4
#define CH    512
#define HW    4096
#define EPS   1e-6f

// ---------------- device scratch (statics; no runtime alloc) ----------------
static __device__ float g_mean[BATCH * 32];
static __device__ float g_rstd[BATCH * 32];
static __device__ __align__(256) __nv_bfloat16 g_xnT_h[(size_t)BATCH * HW * CH];
static __device__ __align__(256) __nv_bfloat16 g_xnT_l[(size_t)BATCH * HW * CH];
static __device__ __align__(256) __nv_bfloat16 g_wqkv_h[3 * CH * CH];
static __device__ __align__(256) __nv_bfloat16 g_wproj_h[CH * CH];
static __device__ __align__(256) __nv_bfloat16 g_qk_h[(size_t)BATCH * HW * 1024];   // q|k [tok][1024]
static __device__ __align__(256) __nv_bfloat16 g_v_h[(size_t)BATCH * CH * HW];      // v [c][tok]
static __device__ __align__(256) float         g_S  [(size_t)BATCH * HW * HW];      // fp32 logits
static __device__ __align__(256) __nv_bfloat16 g_p_h[(size_t)BATCH * HW * HW];      // softmax [i][j]
static __device__ __align__(256) __nv_bfloat16 g_oT_h[(size_t)BATCH * HW * CH];     // O^T [tok][c]

// ---------------- helpers ----------------
__device__ __forceinline__ uint32_t smem_u32(const void* p) {
    uint32_t a;
    asm("{ .reg .u64 t; cvta.to.shared.u64 t, %1; cvt.u32.u64 %0, t; }" : "=r"(a) : "l"(p));
    return a;
}

__device__ __forceinline__ void cp16(uint32_t dst, const void* src) {
    asm volatile("cp.async.cg.shared.global [%0], [%1], 16;" :: "r"(dst), "l"(src));
}
#define CP_COMMIT() asm volatile("cp.async.commit_group;" ::: "memory")
#define CP_WAIT1()  asm volatile("cp.async.wait_group 1;" ::: "memory")
#define CP_WAIT0()  asm volatile("cp.async.wait_group 0;" ::: "memory")

__device__ __forceinline__ void ldm4(uint32_t* r, uint32_t addr) {
    asm volatile("ldmatrix.sync.aligned.m8n8.x4.shared.b16 {%0,%1,%2,%3}, [%4];"
                 : "=r"(r[0]), "=r"(r[1]), "=r"(r[2]), "=r"(r[3]) : "r"(addr));
}

__device__ __forceinline__ void mma16816(float* d, const uint32_t* a, const uint32_t* b) {
    asm volatile(
        "mma.sync.aligned.m16n8k16.row.col.f32.bf16.bf16.f32 "
        "{%0,%1,%2,%3}, {%4,%5,%6,%7}, {%8,%9}, {%0,%1,%2,%3};"
        : "+f"(d[0]), "+f"(d[1]), "+f"(d[2]), "+f"(d[3])
        : "r"(a[0]), "r"(a[1]), "r"(a[2]), "r"(a[3]), "r"(b[0]), "r"(b[1]));
}

__device__ __forceinline__ uint32_t bpack(float a, float b) {
    __nv_bfloat162 t = __floats2bfloat162_rn(a, b);
    return *reinterpret_cast<uint32_t*>(&t);
}
__device__ __forceinline__ float bres(float v) {
    return v - __bfloat162float(__float2bfloat16(v));
}

// ---------------- split-bf16 GEMM: C = A * B^T ----------------
// A: [M][K] hi(/lo if PA) (lda); B: [N][K] hi(/lo if PB) (ldb). Tiles 128x128, K mult of 64.
// passes: ah*bh  (+ ah*bl if PB)  (+ al*bh if PA)
// EPI: 0=QKV  1=S(fp32*alpha, direct reg store)  2=O(bf16 hi row-major)  3=PROJ(transposed+bias+resid)
// smem/stage = (1+PA+1+PB)*16KB; 2 stages. Epilogue (EPI!=1) stages 64 rows at a time (34KB).
template<int EPI, bool PA, bool PB>
__global__ __launch_bounds__(256, (PA && PB) ? 1 : 2) void mma_gemm_kernel(
    const __nv_bfloat16* __restrict__ Ah, const __nv_bfloat16* __restrict__ Al,
    int lda, long long sA,
    const __nv_bfloat16* __restrict__ Bh, const __nv_bfloat16* __restrict__ Bl,
    int ldb, long long sB,
    int K, float alpha, const float* __restrict__ bias,
    float* __restrict__ Cf, long long sCf,
    __nv_bfloat16* __restrict__ Ch, long long sC,
    __nv_bfloat16* __restrict__ Vh, long long sV,
    const float* __restrict__ Res, long long sRes)
{
    constexpr int NA = 1 + (PA ? 1 : 0);
    constexpr int NB = 1 + (PB ? 1 : 0);
    constexpr uint32_t STAGE = (NA + NB) * 16384;

    extern __shared__ char smem[];
    const uint32_t sb = smem_u32(smem);
    const int tid = threadIdx.x, lid = tid & 31, wid = tid >> 5;
    const int bz = blockIdx.z;
    const int m0 = blockIdx.y * 128, n0 = blockIdx.x * 128;

    Ah += (long long)bz * sA;
    if (PA) Al += (long long)bz * sA;
    Bh += (long long)bz * sB;
    if (PB) Bl += (long long)bz * sB;

    const int wm0 = (wid >> 2) * 64, wn0 = (wid & 3) * 32;

    // ---- loader (thread covers seg=tid&7, rows tid>>3 + i*32) ----
    const int l_r0 = tid >> 3, l_seg = tid & 7;
    auto load_stage = [&](int s, int kIter) {
        const uint32_t dst = sb + s * STAGE;
        const int k0 = kIter << 6;
        #pragma unroll
        for (int i = 0; i < 4; i++) {
            const int row = l_r0 + i * 32;
            const uint32_t so = row * 128 + ((l_seg ^ (row & 7)) << 4);
            const size_t ga = (size_t)(m0 + row) * lda + k0 + l_seg * 8;
            const size_t gb = (size_t)(n0 + row) * ldb + k0 + l_seg * 8;
            cp16(dst + so, Ah + ga);
            if (PA) cp16(dst + 16384 + so, Al + ga);
            cp16(dst + NA * 16384 + so, Bh + gb);
            if (PB) cp16(dst + NA * 16384 + 16384 + so, Bl + gb);
        }
    };

    // ---- fragment lane constants ----
    const int matq = lid >> 3, mr = lid & 7;
    const int a_rb = ((matq & 1) << 3) + mr;
    const int a_ks = matq >> 1;
    const int b_rb = (((matq >> 1) & 1) << 3) + mr;
    const int b_ks = matq & 1;

    float acc[4][4][4];
    #pragma unroll
    for (int i = 0; i < 4; i++)
        #pragma unroll
        for (int j = 0; j < 4; j++)
            #pragma unroll
            for (int q = 0; q < 4; q++) acc[i][j][q] = 0.f;

    const int niter = K >> 6;
    load_stage(0, 0); CP_COMMIT();
    load_stage(1, 1); CP_COMMIT();
    CP_WAIT1();
    __syncthreads();

    for (int it = 0; it < niter; it++) {
        const uint32_t Ab = sb + (it & 1) * STAGE;
        #pragma unroll
        for (int ks = 0; ks < 4; ks++) {
            uint32_t ah[4][4], al[4][4], bh[2][4], bl[2][4];
            #pragma unroll
            for (int mt = 0; mt < 4; mt++) {
                const int r = wm0 + mt * 16 + a_rb;
                const uint32_t ad = Ab + r * 128 + (((ks * 2 + a_ks) ^ (r & 7)) << 4);
                ldm4(ah[mt], ad);
                if (PA) ldm4(al[mt], ad + 16384);
            }
            #pragma unroll
            for (int g = 0; g < 2; g++) {
                const int r = wn0 + g * 16 + b_rb;
                const uint32_t bd = Ab + NA * 16384 + r * 128 + (((ks * 2 + b_ks) ^ (r & 7)) << 4);
                ldm4(bh[g], bd);
                if (PB) ldm4(bl[g], bd + 16384);
            }
            #pragma unroll
            for (int mt = 0; mt < 4; mt++)
                #pragma unroll
                for (int nt = 0; nt < 4; nt++) {
                    const uint32_t* bhp = &bh[nt >> 1][(nt & 1) * 2];
                    mma16816(acc[mt][nt], ah[mt], bhp);
                    if (PB) {
                        const uint32_t* blp = &bl[nt >> 1][(nt & 1) * 2];
                        mma16816(acc[mt][nt], ah[mt], blp);
                    }
                    if (PA) mma16816(acc[mt][nt], al[mt], bhp);
                }
        }
        __syncthreads();
        if (it + 2 < niter) {
            load_stage(it & 1, it + 2); CP_COMMIT(); CP_WAIT1();
        } else {
            CP_COMMIT(); CP_WAIT0();
        }
        __syncthreads();
    }

    // ---------------- epilogue ----------------
    if (EPI == 1) {
        // S: direct register store, fp32 * alpha, row-major [i][j]
        float* C = Cf + (size_t)bz * sCf;
        #pragma unroll
        for (int mt = 0; mt < 4; mt++) {
            const int rg = m0 + wm0 + mt * 16 + (lid >> 2);
            #pragma unroll
            for (int nt = 0; nt < 4; nt++) {
                const int c = n0 + wn0 + nt * 8 + ((lid & 3) << 1);
                float2 v0 = make_float2(acc[mt][nt][0] * alpha, acc[mt][nt][1] * alpha);
                float2 v1 = make_float2(acc[mt][nt][2] * alpha, acc[mt][nt][3] * alpha);
                *reinterpret_cast<float2*>(C + (size_t)rg * HW + c)       = v0;
                *reinterpret_cast<float2*>(C + (size_t)(rg + 8) * HW + c) = v1;
            }
        }
        return;
    }

    // staged epilogue in 2 halves of 64 rows (cs = 64x133 floats = 34KB, fits all variants)
    float* cs = reinterpret_cast<float*>(smem);
    #pragma unroll
    for (int h = 0; h < 2; h++) {
        __syncthreads();
        if ((wid >> 2) == h) {
            #pragma unroll
            for (int mt = 0; mt < 4; mt++) {
                const int rl = mt * 16 + (lid >> 2);
                #pragma unroll
                for (int nt = 0; nt < 4; nt++) {
                    const int c = wn0 + nt * 8 + ((lid & 3) << 1);
                    cs[rl * 133 + c]           = acc[mt][nt][0];
                    cs[rl * 133 + c + 1]       = acc[mt][nt][1];
                    cs[(rl + 8) * 133 + c]     = acc[mt][nt][2];
                    cs[(rl + 8) * 133 + c + 1] = acc[mt][nt][3];
                }
            }
        }
        __syncthreads();
        const int mh = m0 + h * 64;

        if (EPI == 0) {
            if (n0 < 1024) {   // q/k: [tok][1024] bf16 hi, +bias
                const float4 bv = *reinterpret_cast<const float4*>(&bias[n0 + lid * 4]);
                __nv_bfloat16* H = Ch + (size_t)bz * sC;
                for (int rl = wid; rl < 64; rl += 8) {
                    const float* row = cs + rl * 133 + lid * 4;
                    const float v0 = row[0] + bv.x, v1 = row[1] + bv.y;
                    const float v2 = row[2] + bv.z, v3 = row[3] + bv.w;
                    const size_t o = (size_t)(mh + rl) * 1024 + n0 + lid * 4;
                    uint2 hi; hi.x = bpack(v0, v1); hi.y = bpack(v2, v3);
                    *reinterpret_cast<uint2*>(H + o) = hi;
                }
            } else {           // v: [c][tok] bf16 hi, +bias (transposed)
                __nv_bfloat16* H = Vh + (size_t)bz * sV;
                for (int c = wid; c < 128; c += 8) {
                    const int n = n0 + c;
                    const float bvn = bias[n];
                    const float v0 = cs[(lid * 2 + 0) * 133 + c] + bvn;
                    const float v1 = cs[(lid * 2 + 1) * 133 + c] + bvn;
                    const size_t o = (size_t)(n - 1024) * HW + mh + lid * 2;
                    *reinterpret_cast<uint32_t*>(H + o) = bpack(v0, v1);
                }
            }
        } else if (EPI == 2) {  // O^T: [tok][c] bf16 hi
            __nv_bfloat16* H = Ch + (size_t)bz * sC;
            for (int rl = wid; rl < 64; rl += 8) {
                const float* row = cs + rl * 133 + lid * 4;
                const size_t o = (size_t)(mh + rl) * CH + n0 + lid * 4;
                uint2 hi; hi.x = bpack(row[0], row[1]); hi.y = bpack(row[2], row[3]);
                *reinterpret_cast<uint2*>(H + o) = hi;
            }
        } else {                // PROJ: out[c][tok] = tile^T + bias + residual (fp32)
            const float* R = Res + (size_t)bz * sRes;
            float* C = Cf + (size_t)bz * sCf;
            for (int c = wid; c < 128; c += 8) {
                const int n = n0 + c;
                const float bvn = bias[n];
                const size_t o = (size_t)n * HW + mh + lid * 2;
                const float2 rr = *reinterpret_cast<const float2*>(R + o);
                float2 v;
                v.x = cs[(lid * 2 + 0) * 133 + c] + bvn + rr.x;
                v.y = cs[(lid * 2 + 1) * 133 + c] + bvn + rr.y;
                *reinterpret_cast<float2*>(C + o) = v;
            }
        }
    }
}

// ---------------- GroupNorm stats ----------------
__global__ __launch_bounds__(256) void gn_stats_kernel(const float* __restrict__ x)
{
    const int bg = blockIdx.x;
    const size_t base = (size_t)bg * 16 * HW;
    const int n = 16 * HW;
    float s = 0.f, ss = 0.f;
    for (int i = threadIdx.x; i < n; i += 256) {
        float v = x[base + i];
        s += v; ss += v * v;
    }
    #pragma unroll
    for (int o = 16; o > 0; o >>= 1) {
        s  += __shfl_xor_sync(0xffffffffu, s,  o);
        ss += __shfl_xor_sync(0xffffffffu, ss, o);
    }
    __shared__ float sh[16];
    const int w = threadIdx.x >> 5, l = threadIdx.x & 31;
    if (l == 0) { sh[w] = s; sh[8 + w] = ss; }
    __syncthreads();
    if (threadIdx.x == 0) {
        float S = 0.f, SS = 0.f;
        #pragma unroll
        for (int i = 0; i < 8; i++) { S += sh[i]; SS += sh[8 + i]; }
        float mean = S / (float)n;
        float var  = SS / (float)n - mean * mean;
        g_mean[bg] = mean;
        g_rstd[bg] = rsqrtf(var + EPS);
    }
}

// ---------------- normalize + transpose + bf16 split ----------------
__global__ __launch_bounds__(256) void normT_kernel(
    const float* __restrict__ x, const float* __restrict__ gamma,
    const float* __restrict__ beta,
    __nv_bfloat16* __restrict__ th, __nv_bfloat16* __restrict__ tl)
{
    __shared__ float tile[64][65];
    const int b = blockIdx.z, c0 = blockIdx.y * 64, t0 = blockIdx.x * 64;
    const int lane = threadIdx.x & 63, r0 = threadIdx.x >> 6;
    #pragma unroll
    for (int r = r0; r < 64; r += 4) {
        const int c = c0 + r;
        const int gr = b * 32 + (c >> 4);
        float v = x[((size_t)b * CH + c) * HW + t0 + lane];
        tile[r][lane] = (v - g_mean[gr]) * g_rstd[gr] * gamma[c] + beta[c];
    }
    __syncthreads();
    #pragma unroll
    for (int r = r0; r < 64; r += 4) {
        const float v = tile[lane][r];
        const size_t o = ((size_t)b * HW + t0 + r) * CH + c0 + lane;
        __nv_bfloat16 hv = __float2bfloat16(v);
        th[o] = hv;
        tl[o] = __float2bfloat16(v - __bfloat162float(hv));
    }
}

// ---------------- weight fp32 -> hi(/lo) split ----------------
__global__ void wsplit_kernel(const float* __restrict__ in,
                              __nv_bfloat16* __restrict__ h,
                              __nv_bfloat16* __restrict__ l, int n)
{
    int i = blockIdx.x * 256 + threadIdx.x;
    if (i < n) {
        float v = in[i];
        __nv_bfloat16 hv = __float2bfloat16(v);
        h[i] = hv;
        if (l) l[i] = __float2bfloat16(v - __bfloat162float(hv));
    }
}

// ---------------- softmax (fp32 in, bf16 hi out) ----------------
__global__ __launch_bounds__(256) void softmax_kernel(
    const float* __restrict__ S, __nv_bfloat16* __restrict__ ph)
{
    const size_t base = (size_t)blockIdx.x * HW;
    const float* p = S + base;

    float v[16];
    float mx = -INFINITY;
    #pragma unroll
    for (int i = 0; i < 16; i++) {
        v[i] = p[threadIdx.x + i * 256];
        mx = fmaxf(mx, v[i]);
    }
    #pragma unroll
    for (int o = 16; o > 0; o >>= 1)
        mx = fmaxf(mx, __shfl_xor_sync(0xffffffffu, mx, o));

    __shared__ float sh[10];
    const int w = threadIdx.x >> 5, l = threadIdx.x & 31;
    if (l == 0) sh[w] = mx;
    __syncthreads();
    if (threadIdx.x == 0) {
        float m = sh[0];
        #pragma unroll
        for (int i = 1; i < 8; i++) m = fmaxf(m, sh[i]);
        sh[8] = m;
    }
    __syncthreads();
    mx = sh[8];

    float sum = 0.f;
    #pragma unroll
    for (int i = 0; i < 16; i++) { v[i] = __expf(v[i] - mx); sum += v[i]; }
    #pragma unroll
    for (int o = 16; o > 0; o >>= 1)
        sum += __shfl_xor_sync(0xffffffffu, sum, o);
    if (l == 0) sh[w] = sum;
    __syncthreads();
    if (threadIdx.x == 0) {
        float s = 0.f;
        #pragma unroll
        for (int i = 0; i < 8; i++) s += sh[i];
        sh[9] = 1.f / s;
    }
    __syncthreads();
    const float inv = sh[9];

    #pragma unroll
    for (int i = 0; i < 16; i++) {
        const size_t o = base + threadIdx.x + i * 256;
        ph[o] = __float2bfloat16(v[i] * inv);
    }
}

// ---------------- launch ----------------
extern "C" void kernel_launch(void* const* d_in, const int* in_sizes, int n_in,
                              void* d_out, int out_size)
{
    const float* x      = (const float*)d_in[0];
    const float* gamma  = (const float*)d_in[1];
    const float* beta   = (const float*)d_in[2];
    const float* w_qkv  = (const float*)d_in[3];
    const float* b_qkv  = (const float*)d_in[4];
    const float* w_proj = (const float*)d_in[5];
    const float* b_proj = (const float*)d_in[6];
    float* out = (float*)d_out;

    __nv_bfloat16 *xnT_h, *xnT_l, *wqkv_h, *wproj_h;
    __nv_bfloat16 *qk_h, *v_h, *p_h, *oT_h;
    float* S;
    cudaGetSymbolAddress((void**)&xnT_h, g_xnT_h);
    cudaGetSymbolAddress((void**)&xnT_l, g_xnT_l);
    cudaGetSymbolAddress((void**)&wqkv_h, g_wqkv_h);
    cudaGetSymbolAddress((void**)&wproj_h, g_wproj_h);
    cudaGetSymbolAddress((void**)&qk_h, g_qk_h);
    cudaGetSymbolAddress((void**)&v_h, g_v_h);
    cudaGetSymbolAddress((void**)&S, g_S);
    cudaGetSymbolAddress((void**)&p_h, g_p_h);
    cudaGetSymbolAddress((void**)&oT_h, g_oT_h);

    const int SM_QKV  = 3 * 16384 * 2;   // 96KB  (2 CTAs/SM)
    const int SM_SO   = 2 * 16384 * 2;   // 64KB  (2 CTAs/SM)

    cudaFuncSetAttribute((const void*)mma_gemm_kernel<0, true, false>,  cudaFuncAttributeMaxDynamicSharedMemorySize, SM_QKV);
    cudaFuncSetAttribute((const void*)mma_gemm_kernel<1, false, false>, cudaFuncAttributeMaxDynamicSharedMemorySize, SM_SO);
    cudaFuncSetAttribute((const void*)mma_gemm_kernel<2, false, false>, cudaFuncAttributeMaxDynamicSharedMemorySize, SM_SO);
    cudaFuncSetAttribute((const void*)mma_gemm_kernel<3, false, false>, cudaFuncAttributeMaxDynamicSharedMemorySize, SM_SO);

    const long long sTok = (long long)HW * CH;
    const long long sQK  = (long long)HW * 1024;
    const long long sS   = (long long)HW * HW;
    const float scale2 = 1.f / sqrtf((float)CH);

    // 1) weight splits (hi only)
    wsplit_kernel<<<(3 * CH * CH + 255) / 256, 256>>>(w_qkv, wqkv_h, nullptr, 3 * CH * CH);
    wsplit_kernel<<<(CH * CH + 255) / 256, 256>>>(w_proj, wproj_h, nullptr, CH * CH);

    // 2) GroupNorm stats + normalize/transpose/split
    gn_stats_kernel<<<BATCH * 32, 256>>>(x);
    normT_kernel<<<dim3(HW / 64, CH / 64, BATCH), 256>>>(x, gamma, beta, xnT_h, xnT_l);

    // 3) QKV (2-pass: (xh+xl)*wh): C[tok][oc] = xnT . w_qkv^T  (M=4096, N=1536, K=512)
    mma_gemm_kernel<0, true, false><<<dim3(12, 32, BATCH), 256, SM_QKV>>>(
        xnT_h, xnT_l, CH, sTok, wqkv_h, nullptr, CH, 0,
        CH, 1.f, b_qkv,
        nullptr, 0, qk_h, sQK, v_h, sTok, nullptr, 0);

    // 4) S (1-pass): S[i][j] = qh . kh^T * scale  (M=N=4096, K=512)
    mma_gemm_kernel<1, false, false><<<dim3(32, 32, BATCH), 256, SM_SO>>>(
        qk_h, nullptr, 1024, sQK, qk_h + CH, nullptr, 1024, sQK,
        CH, scale2, nullptr,
        S, sS, nullptr, 0, nullptr, 0, nullptr, 0);

    // 5) softmax rows -> p hi
    softmax_kernel<<<BATCH * HW, 256>>>(S, p_h);

    // 6) O (1-pass): O^T[tok][c] = ph . vh^T  (M=4096, N=512, K=4096)
    mma_gemm_kernel<2, false, false><<<dim3(4, 32, BATCH), 256, SM_SO>>>(
        p_h, nullptr, HW, sS, v_h, nullptr, HW, sTok,
        HW, 1.f, nullptr,
        nullptr, 0, oT_h, sTok, nullptr, 0, nullptr, 0);

    // 7) PROJ (1-pass): out[c][tok] = oT . w_proj^T + b_proj + x  (M=4096, N=512, K=512)
    mma_gemm_kernel<3, false, false><<<dim3(4, 32, BATCH), 256, SM_SO>>>(
        oT_h, nullptr, CH, sTok, wproj_h, nullptr, CH, 0,
        CH, 1.f, b_proj,
        out, sTok, nullptr, 0, nullptr, 0, x, sTok);
}

// round 15
// speedup vs baseline: 2.1134x; 1.0913x over previous
#include <cuda_runtime.h>
#include <cuda_bf16.h>
#include <math.h>
#include <stdint.h>

#define BATCH 4
#define CH    512
#define HW    4096
#define EPS   1e-6f

// ---------------- device scratch (statics; no runtime alloc) ----------------
static __device__ float g_mean[BATCH * 32];
static __device__ float g_rstd[BATCH * 32];
static __device__ __align__(256) __nv_bfloat16 g_xnT_h[(size_t)BATCH * HW * CH];
static __device__ __align__(256) __nv_bfloat16 g_wqkv_h[3 * CH * CH];
static __device__ __align__(256) __nv_bfloat16 g_wproj_h[CH * CH];
static __device__ __align__(256) __nv_bfloat16 g_qk_h[(size_t)BATCH * HW * 1024];   // q|k [tok][1024]
static __device__ __align__(256) __nv_bfloat16 g_v_h[(size_t)BATCH * CH * HW];      // v [c][tok]
static __device__ __align__(256) float         g_S  [(size_t)BATCH * HW * HW];      // fp32 logits
static __device__ __align__(256) __nv_bfloat16 g_p_h[(size_t)BATCH * HW * HW];      // softmax [i][j]
static __device__ __align__(256) __nv_bfloat16 g_oT_h[(size_t)BATCH * HW * CH];     // O^T [tok][c]

// ---------------- helpers ----------------
__device__ __forceinline__ uint32_t smem_u32(const void* p) {
    uint32_t a;
    asm("{ .reg .u64 t; cvta.to.shared.u64 t, %1; cvt.u32.u64 %0, t; }" : "=r"(a) : "l"(p));
    return a;
}

__device__ __forceinline__ void cp16(uint32_t dst, const void* src) {
    asm volatile("cp.async.cg.shared.global [%0], [%1], 16;" :: "r"(dst), "l"(src));
}
#define CP_COMMIT() asm volatile("cp.async.commit_group;" ::: "memory")
#define CP_WAIT1()  asm volatile("cp.async.wait_group 1;" ::: "memory")
#define CP_WAIT0()  asm volatile("cp.async.wait_group 0;" ::: "memory")

__device__ __forceinline__ void ldm4(uint32_t* r, uint32_t addr) {
    asm volatile("ldmatrix.sync.aligned.m8n8.x4.shared.b16 {%0,%1,%2,%3}, [%4];"
                 : "=r"(r[0]), "=r"(r[1]), "=r"(r[2]), "=r"(r[3]) : "r"(addr));
}

__device__ __forceinline__ void mma16816(float* d, const uint32_t* a, const uint32_t* b) {
    asm volatile(
        "mma.sync.aligned.m16n8k16.row.col.f32.bf16.bf16.f32 "
        "{%0,%1,%2,%3}, {%4,%5,%6,%7}, {%8,%9}, {%0,%1,%2,%3};"
        : "+f"(d[0]), "+f"(d[1]), "+f"(d[2]), "+f"(d[3])
        : "r"(a[0]), "r"(a[1]), "r"(a[2]), "r"(a[3]), "r"(b[0]), "r"(b[1]));
}

__device__ __forceinline__ uint32_t bpack(float a, float b) {
    __nv_bfloat162 t = __floats2bfloat162_rn(a, b);
    return *reinterpret_cast<uint32_t*>(&t);
}

// ---------------- split-bf16 GEMM: C = A * B^T ----------------
// A: [M][K] hi(/lo if PA) (lda); B: [N][K] hi(/lo if PB) (ldb). Tiles 128x128, K mult of 64.
// passes: ah*bh  (+ ah*bl if PB)  (+ al*bh if PA)
// EPI: 0=QKV  1=S(fp32*alpha, direct reg store)  2=O(bf16 hi row-major)  3=PROJ(transposed+bias+resid)
// smem/stage = (1+PA+1+PB)*16KB; 2 stages. Epilogue (EPI!=1) stages 64 rows at a time (34KB).
template<int EPI, bool PA, bool PB>
__global__ __launch_bounds__(256, (PA && PB) ? 1 : 2) void mma_gemm_kernel(
    const __nv_bfloat16* __restrict__ Ah, const __nv_bfloat16* __restrict__ Al,
    int lda, long long sA,
    const __nv_bfloat16* __restrict__ Bh, const __nv_bfloat16* __restrict__ Bl,
    int ldb, long long sB,
    int K, float alpha, const float* __restrict__ bias,
    float* __restrict__ Cf, long long sCf,
    __nv_bfloat16* __restrict__ Ch, long long sC,
    __nv_bfloat16* __restrict__ Vh, long long sV,
    const float* __restrict__ Res, long long sRes)
{
    constexpr int NA = 1 + (PA ? 1 : 0);
    constexpr int NB = 1 + (PB ? 1 : 0);
    constexpr uint32_t STAGE = (NA + NB) * 16384;

    extern __shared__ char smem[];
    const uint32_t sb = smem_u32(smem);
    const int tid = threadIdx.x, lid = tid & 31, wid = tid >> 5;
    const int bz = blockIdx.z;
    const int m0 = blockIdx.y * 128, n0 = blockIdx.x * 128;

    Ah += (long long)bz * sA;
    if (PA) Al += (long long)bz * sA;
    Bh += (long long)bz * sB;
    if (PB) Bl += (long long)bz * sB;

    const int wm0 = (wid >> 2) * 64, wn0 = (wid & 3) * 32;

    // ---- loader (thread covers seg=tid&7, rows tid>>3 + i*32) ----
    const int l_r0 = tid >> 3, l_seg = tid & 7;
    auto load_stage = [&](int s, int kIter) {
        const uint32_t dst = sb + s * STAGE;
        const int k0 = kIter << 6;
        #pragma unroll
        for (int i = 0; i < 4; i++) {
            const int row = l_r0 + i * 32;
            const uint32_t so = row * 128 + ((l_seg ^ (row & 7)) << 4);
            const size_t ga = (size_t)(m0 + row) * lda + k0 + l_seg * 8;
            const size_t gb = (size_t)(n0 + row) * ldb + k0 + l_seg * 8;
            cp16(dst + so, Ah + ga);
            if (PA) cp16(dst + 16384 + so, Al + ga);
            cp16(dst + NA * 16384 + so, Bh + gb);
            if (PB) cp16(dst + NA * 16384 + 16384 + so, Bl + gb);
        }
    };

    // ---- fragment lane constants ----
    const int matq = lid >> 3, mr = lid & 7;
    const int a_rb = ((matq & 1) << 3) + mr;
    const int a_ks = matq >> 1;
    const int b_rb = (((matq >> 1) & 1) << 3) + mr;
    const int b_ks = matq & 1;

    float acc[4][4][4];
    #pragma unroll
    for (int i = 0; i < 4; i++)
        #pragma unroll
        for (int j = 0; j < 4; j++)
            #pragma unroll
            for (int q = 0; q < 4; q++) acc[i][j][q] = 0.f;

    const int niter = K >> 6;
    load_stage(0, 0); CP_COMMIT();
    load_stage(1, 1); CP_COMMIT();
    CP_WAIT1();
    __syncthreads();

    for (int it = 0; it < niter; it++) {
        const uint32_t Ab = sb + (it & 1) * STAGE;
        #pragma unroll
        for (int ks = 0; ks < 4; ks++) {
            uint32_t ah[4][4], al[4][4], bh[2][4], bl[2][4];
            #pragma unroll
            for (int mt = 0; mt < 4; mt++) {
                const int r = wm0 + mt * 16 + a_rb;
                const uint32_t ad = Ab + r * 128 + (((ks * 2 + a_ks) ^ (r & 7)) << 4);
                ldm4(ah[mt], ad);
                if (PA) ldm4(al[mt], ad + 16384);
            }
            #pragma unroll
            for (int g = 0; g < 2; g++) {
                const int r = wn0 + g * 16 + b_rb;
                const uint32_t bd = Ab + NA * 16384 + r * 128 + (((ks * 2 + b_ks) ^ (r & 7)) << 4);
                ldm4(bh[g], bd);
                if (PB) ldm4(bl[g], bd + 16384);
            }
            #pragma unroll
            for (int mt = 0; mt < 4; mt++)
                #pragma unroll
                for (int nt = 0; nt < 4; nt++) {
                    const uint32_t* bhp = &bh[nt >> 1][(nt & 1) * 2];
                    mma16816(acc[mt][nt], ah[mt], bhp);
                    if (PB) {
                        const uint32_t* blp = &bl[nt >> 1][(nt & 1) * 2];
                        mma16816(acc[mt][nt], ah[mt], blp);
                    }
                    if (PA) mma16816(acc[mt][nt], al[mt], bhp);
                }
        }
        __syncthreads();
        if (it + 2 < niter) {
            load_stage(it & 1, it + 2); CP_COMMIT(); CP_WAIT1();
        } else {
            CP_COMMIT(); CP_WAIT0();
        }
        __syncthreads();
    }

    // ---------------- epilogue ----------------
    if (EPI == 1) {
        // S: direct register store, fp32 * alpha, row-major [i][j]
        float* C = Cf + (size_t)bz * sCf;
        #pragma unroll
        for (int mt = 0; mt < 4; mt++) {
            const int rg = m0 + wm0 + mt * 16 + (lid >> 2);
            #pragma unroll
            for (int nt = 0; nt < 4; nt++) {
                const int c = n0 + wn0 + nt * 8 + ((lid & 3) << 1);
                float2 v0 = make_float2(acc[mt][nt][0] * alpha, acc[mt][nt][1] * alpha);
                float2 v1 = make_float2(acc[mt][nt][2] * alpha, acc[mt][nt][3] * alpha);
                *reinterpret_cast<float2*>(C + (size_t)rg * HW + c)       = v0;
                *reinterpret_cast<float2*>(C + (size_t)(rg + 8) * HW + c) = v1;
            }
        }
        return;
    }

    // staged epilogue in 2 halves of 64 rows (cs = 64x133 floats = 34KB, fits all variants)
    float* cs = reinterpret_cast<float*>(smem);
    #pragma unroll
    for (int h = 0; h < 2; h++) {
        __syncthreads();
        if ((wid >> 2) == h) {
            #pragma unroll
            for (int mt = 0; mt < 4; mt++) {
                const int rl = mt * 16 + (lid >> 2);
                #pragma unroll
                for (int nt = 0; nt < 4; nt++) {
                    const int c = wn0 + nt * 8 + ((lid & 3) << 1);
                    cs[rl * 133 + c]           = acc[mt][nt][0];
                    cs[rl * 133 + c + 1]       = acc[mt][nt][1];
                    cs[(rl + 8) * 133 + c]     = acc[mt][nt][2];
                    cs[(rl + 8) * 133 + c + 1] = acc[mt][nt][3];
                }
            }
        }
        __syncthreads();
        const int mh = m0 + h * 64;

        if (EPI == 0) {
            if (n0 < 1024) {   // q/k: [tok][1024] bf16 hi, +bias
                const float4 bv = *reinterpret_cast<const float4*>(&bias[n0 + lid * 4]);
                __nv_bfloat16* H = Ch + (size_t)bz * sC;
                for (int rl = wid; rl < 64; rl += 8) {
                    const float* row = cs + rl * 133 + lid * 4;
                    const float v0 = row[0] + bv.x, v1 = row[1] + bv.y;
                    const float v2 = row[2] + bv.z, v3 = row[3] + bv.w;
                    const size_t o = (size_t)(mh + rl) * 1024 + n0 + lid * 4;
                    uint2 hi; hi.x = bpack(v0, v1); hi.y = bpack(v2, v3);
                    *reinterpret_cast<uint2*>(H + o) = hi;
                }
            } else {           // v: [c][tok] bf16 hi, +bias (transposed)
                __nv_bfloat16* H = Vh + (size_t)bz * sV;
                for (int c = wid; c < 128; c += 8) {
                    const int n = n0 + c;
                    const float bvn = bias[n];
                    const float v0 = cs[(lid * 2 + 0) * 133 + c] + bvn;
                    const float v1 = cs[(lid * 2 + 1) * 133 + c] + bvn;
                    const size_t o = (size_t)(n - 1024) * HW + mh + lid * 2;
                    *reinterpret_cast<uint32_t*>(H + o) = bpack(v0, v1);
                }
            }
        } else if (EPI == 2) {  // O^T: [tok][c] bf16 hi
            __nv_bfloat16* H = Ch + (size_t)bz * sC;
            for (int rl = wid; rl < 64; rl += 8) {
                const float* row = cs + rl * 133 + lid * 4;
                const size_t o = (size_t)(mh + rl) * CH + n0 + lid * 4;
                uint2 hi; hi.x = bpack(row[0], row[1]); hi.y = bpack(row[2], row[3]);
                *reinterpret_cast<uint2*>(H + o) = hi;
            }
        } else {                // PROJ: out[c][tok] = tile^T + bias + residual (fp32)
            const float* R = Res + (size_t)bz * sRes;
            float* C = Cf + (size_t)bz * sCf;
            for (int c = wid; c < 128; c += 8) {
                const int n = n0 + c;
                const float bvn = bias[n];
                const size_t o = (size_t)n * HW + mh + lid * 2;
                const float2 rr = *reinterpret_cast<const float2*>(R + o);
                float2 v;
                v.x = cs[(lid * 2 + 0) * 133 + c] + bvn + rr.x;
                v.y = cs[(lid * 2 + 1) * 133 + c] + bvn + rr.y;
                *reinterpret_cast<float2*>(C + o) = v;
            }
        }
    }
}

// ---------------- GroupNorm stats ----------------
__global__ __launch_bounds__(256) void gn_stats_kernel(const float* __restrict__ x)
{
    const int bg = blockIdx.x;
    const size_t base = (size_t)bg * 16 * HW;
    const int n = 16 * HW;
    float s = 0.f, ss = 0.f;
    for (int i = threadIdx.x; i < n; i += 256) {
        float v = x[base + i];
        s += v; ss += v * v;
    }
    #pragma unroll
    for (int o = 16; o > 0; o >>= 1) {
        s  += __shfl_xor_sync(0xffffffffu, s,  o);
        ss += __shfl_xor_sync(0xffffffffu, ss, o);
    }
    __shared__ float sh[16];
    const int w = threadIdx.x >> 5, l = threadIdx.x & 31;
    if (l == 0) { sh[w] = s; sh[8 + w] = ss; }
    __syncthreads();
    if (threadIdx.x == 0) {
        float S = 0.f, SS = 0.f;
        #pragma unroll
        for (int i = 0; i < 8; i++) { S += sh[i]; SS += sh[8 + i]; }
        float mean = S / (float)n;
        float var  = SS / (float)n - mean * mean;
        g_mean[bg] = mean;
        g_rstd[bg] = rsqrtf(var + EPS);
    }
}

// ---------------- normalize + transpose + bf16 (hi only) ----------------
__global__ __launch_bounds__(256) void normT_kernel(
    const float* __restrict__ x, const float* __restrict__ gamma,
    const float* __restrict__ beta,
    __nv_bfloat16* __restrict__ th)
{
    __shared__ float tile[64][65];
    const int b = blockIdx.z, c0 = blockIdx.y * 64, t0 = blockIdx.x * 64;
    const int lane = threadIdx.x & 63, r0 = threadIdx.x >> 6;
    #pragma unroll
    for (int r = r0; r < 64; r += 4) {
        const int c = c0 + r;
        const int gr = b * 32 + (c >> 4);
        float v = x[((size_t)b * CH + c) * HW + t0 + lane];
        tile[r][lane] = (v - g_mean[gr]) * g_rstd[gr] * gamma[c] + beta[c];
    }
    __syncthreads();
    #pragma unroll
    for (int r = r0; r < 64; r += 4) {
        const size_t o = ((size_t)b * HW + t0 + r) * CH + c0 + lane;
        th[o] = __float2bfloat16(tile[lane][r]);
    }
}

// ---------------- weight fp32 -> bf16 hi ----------------
__global__ void wsplit_kernel(const float* __restrict__ in,
                              __nv_bfloat16* __restrict__ h, int n)
{
    int i = blockIdx.x * 256 + threadIdx.x;
    if (i < n) h[i] = __float2bfloat16(in[i]);
}

// ---------------- softmax (fp32 in, bf16 hi out) ----------------
__global__ __launch_bounds__(256) void softmax_kernel(
    const float* __restrict__ S, __nv_bfloat16* __restrict__ ph)
{
    const size_t base = (size_t)blockIdx.x * HW;
    const float* p = S + base;

    float v[16];
    float mx = -INFINITY;
    #pragma unroll
    for (int i = 0; i < 16; i++) {
        v[i] = p[threadIdx.x + i * 256];
        mx = fmaxf(mx, v[i]);
    }
    #pragma unroll
    for (int o = 16; o > 0; o >>= 1)
        mx = fmaxf(mx, __shfl_xor_sync(0xffffffffu, mx, o));

    __shared__ float sh[10];
    const int w = threadIdx.x >> 5, l = threadIdx.x & 31;
    if (l == 0) sh[w] = mx;
    __syncthreads();
    if (threadIdx.x == 0) {
        float m = sh[0];
        #pragma unroll
        for (int i = 1; i < 8; i++) m = fmaxf(m, sh[i]);
        sh[8] = m;
    }
    __syncthreads();
    mx = sh[8];

    float sum = 0.f;
    #pragma unroll
    for (int i = 0; i < 16; i++) { v[i] = __expf(v[i] - mx); sum += v[i]; }
    #pragma unroll
    for (int o = 16; o > 0; o >>= 1)
        sum += __shfl_xor_sync(0xffffffffu, sum, o);
    if (l == 0) sh[w] = sum;
    __syncthreads();
    if (threadIdx.x == 0) {
        float s = 0.f;
        #pragma unroll
        for (int i = 0; i < 8; i++) s += sh[i];
        sh[9] = 1.f / s;
    }
    __syncthreads();
    const float inv = sh[9];

    #pragma unroll
    for (int i = 0; i < 16; i++) {
        const size_t o = base + threadIdx.x + i * 256;
        ph[o] = __float2bfloat16(v[i] * inv);
    }
}

// ---------------- launch ----------------
extern "C" void kernel_launch(void* const* d_in, const int* in_sizes, int n_in,
                              void* d_out, int out_size)
{
    const float* x      = (const float*)d_in[0];
    const float* gamma  = (const float*)d_in[1];
    const float* beta   = (const float*)d_in[2];
    const float* w_qkv  = (const float*)d_in[3];
    const float* b_qkv  = (const float*)d_in[4];
    const float* w_proj = (const float*)d_in[5];
    const float* b_proj = (const float*)d_in[6];
    float* out = (float*)d_out;

    __nv_bfloat16 *xnT_h, *wqkv_h, *wproj_h;
    __nv_bfloat16 *qk_h, *v_h, *p_h, *oT_h;
    float* S;
    cudaGetSymbolAddress((void**)&xnT_h, g_xnT_h);
    cudaGetSymbolAddress((void**)&wqkv_h, g_wqkv_h);
    cudaGetSymbolAddress((void**)&wproj_h, g_wproj_h);
    cudaGetSymbolAddress((void**)&qk_h, g_qk_h);
    cudaGetSymbolAddress((void**)&v_h, g_v_h);
    cudaGetSymbolAddress((void**)&S, g_S);
    cudaGetSymbolAddress((void**)&p_h, g_p_h);
    cudaGetSymbolAddress((void**)&oT_h, g_oT_h);

    const int SM_SO = 2 * 16384 * 2;   // 64KB (2 CTAs/SM)

    cudaFuncSetAttribute((const void*)mma_gemm_kernel<0, false, false>, cudaFuncAttributeMaxDynamicSharedMemorySize, SM_SO);
    cudaFuncSetAttribute((const void*)mma_gemm_kernel<1, false, false>, cudaFuncAttributeMaxDynamicSharedMemorySize, SM_SO);
    cudaFuncSetAttribute((const void*)mma_gemm_kernel<2, false, false>, cudaFuncAttributeMaxDynamicSharedMemorySize, SM_SO);
    cudaFuncSetAttribute((const void*)mma_gemm_kernel<3, false, false>, cudaFuncAttributeMaxDynamicSharedMemorySize, SM_SO);

    const long long sTok = (long long)HW * CH;
    const long long sQK  = (long long)HW * 1024;
    const long long sS   = (long long)HW * HW;
    const float scale2 = 1.f / sqrtf((float)CH);

    // 1) weight conversions (bf16 hi)
    wsplit_kernel<<<(3 * CH * CH + 255) / 256, 256>>>(w_qkv, wqkv_h, 3 * CH * CH);
    wsplit_kernel<<<(CH * CH + 255) / 256, 256>>>(w_proj, wproj_h, CH * CH);

    // 2) GroupNorm stats + normalize/transpose
    gn_stats_kernel<<<BATCH * 32, 256>>>(x);
    normT_kernel<<<dim3(HW / 64, CH / 64, BATCH), 256>>>(x, gamma, beta, xnT_h);

    // 3) QKV (1-pass): C[tok][oc] = xnT . w_qkv^T  (M=4096, N=1536, K=512)
    mma_gemm_kernel<0, false, false><<<dim3(12, 32, BATCH), 256, SM_SO>>>(
        xnT_h, nullptr, CH, sTok, wqkv_h, nullptr, CH, 0,
        CH, 1.f, b_qkv,
        nullptr, 0, qk_h, sQK, v_h, sTok, nullptr, 0);

    // 4) S (1-pass): S[i][j] = qh . kh^T * scale  (M=N=4096, K=512)
    mma_gemm_kernel<1, false, false><<<dim3(32, 32, BATCH), 256, SM_SO>>>(
        qk_h, nullptr, 1024, sQK, qk_h + CH, nullptr, 1024, sQK,
        CH, scale2, nullptr,
        S, sS, nullptr, 0, nullptr, 0, nullptr, 0);

    // 5) softmax rows -> p hi
    softmax_kernel<<<BATCH * HW, 256>>>(S, p_h);

    // 6) O (1-pass): O^T[tok][c] = ph . vh^T  (M=4096, N=512, K=4096)
    mma_gemm_kernel<2, false, false><<<dim3(4, 32, BATCH), 256, SM_SO>>>(
        p_h, nullptr, HW, sS, v_h, nullptr, HW, sTok,
        HW, 1.f, nullptr,
        nullptr, 0, oT_h, sTok, nullptr, 0, nullptr, 0);

    // 7) PROJ (1-pass): out[c][tok] = oT . w_proj^T + b_proj + x  (M=4096, N=512, K=512)
    mma_gemm_kernel<3, false, false><<<dim3(4, 32, BATCH), 256, SM_SO>>>(
        oT_h, nullptr, CH, sTok, wproj_h, nullptr, CH, 0,
        CH, 1.f, b_proj,
        out, sTok, nullptr, 0, nullptr, 0, x, sTok);
}

// round 17
// speedup vs baseline: 2.2604x; 1.0695x over previous
#include <cuda_runtime.h>
#include <cuda_bf16.h>
#include <math.h>
#include <stdint.h>

#define BATCH 4
#define CH    512
#define HW    4096
#define EPS   1e-6f

// ---------------- device scratch (statics; no runtime alloc) ----------------
static __device__ float g_mean[BATCH * 32];
static __device__ float g_rstd[BATCH * 32];
static __device__ __align__(256) __nv_bfloat16 g_xnT_h[(size_t)BATCH * HW * CH];
static __device__ __align__(256) __nv_bfloat16 g_wqkv_h[3 * CH * CH];
static __device__ __align__(256) __nv_bfloat16 g_wproj_h[CH * CH];
static __device__ __align__(256) __nv_bfloat16 g_qk_h[(size_t)BATCH * HW * 1024];   // q|k [tok][1024]
static __device__ __align__(256) __nv_bfloat16 g_v_h[(size_t)BATCH * CH * HW];      // v [c][tok]
static __device__ __align__(256) __nv_bfloat16 g_e  [(size_t)BATCH * HW * HW];      // unnormalized exp(S) bf16
static __device__ __align__(256) float         g_part[(size_t)BATCH * HW * 32];     // per-(row,tileX) exp sums
static __device__ __align__(256) float         g_inv [(size_t)BATCH * HW];          // 1/rowsum
static __device__ __align__(256) __nv_bfloat16 g_oT_h[(size_t)BATCH * HW * CH];     // O^T [tok][c]

// ---------------- helpers ----------------
__device__ __forceinline__ uint32_t smem_u32(const void* p) {
    uint32_t a;
    asm("{ .reg .u64 t; cvta.to.shared.u64 t, %1; cvt.u32.u64 %0, t; }" : "=r"(a) : "l"(p));
    return a;
}

__device__ __forceinline__ void cp16(uint32_t dst, const void* src) {
    asm volatile("cp.async.cg.shared.global [%0], [%1], 16;" :: "r"(dst), "l"(src));
}
#define CP_COMMIT() asm volatile("cp.async.commit_group;" ::: "memory")
#define CP_WAIT1()  asm volatile("cp.async.wait_group 1;" ::: "memory")
#define CP_WAIT0()  asm volatile("cp.async.wait_group 0;" ::: "memory")

__device__ __forceinline__ void ldm4(uint32_t* r, uint32_t addr) {
    asm volatile("ldmatrix.sync.aligned.m8n8.x4.shared.b16 {%0,%1,%2,%3}, [%4];"
                 : "=r"(r[0]), "=r"(r[1]), "=r"(r[2]), "=r"(r[3]) : "r"(addr));
}

__device__ __forceinline__ void mma16816(float* d, const uint32_t* a, const uint32_t* b) {
    asm volatile(
        "mma.sync.aligned.m16n8k16.row.col.f32.bf16.bf16.f32 "
        "{%0,%1,%2,%3}, {%4,%5,%6,%7}, {%8,%9}, {%0,%1,%2,%3};"
        : "+f"(d[0]), "+f"(d[1]), "+f"(d[2]), "+f"(d[3])
        : "r"(a[0]), "r"(a[1]), "r"(a[2]), "r"(a[3]), "r"(b[0]), "r"(b[1]));
}

__device__ __forceinline__ uint32_t bpack(float a, float b) {
    __nv_bfloat162 t = __floats2bfloat162_rn(a, b);
    return *reinterpret_cast<uint32_t*>(&t);
}

// ---------------- 1-pass bf16 GEMM: C = A * B^T ----------------
// A: [M][K] bf16 (lda); B: [N][K] bf16 (ldb). Tiles 128x128, K mult of 64.
// EPI: 0=QKV (q/k rows + v transposed, +bias)
//      1=S-exp: e=exp(s*alpha) bf16 + per-(row,tileX) sum partials
//      2=O (bf16 row-major, rows scaled by Inv[tok])
//      3=PROJ (transposed + bias + residual, fp32)
// smem = 2 stages x 32KB; epilogue stages 64 rows (34KB).
template<int EPI>
__global__ __launch_bounds__(256, 2) void mma_gemm_kernel(
    const __nv_bfloat16* __restrict__ Ah, int lda, long long sA,
    const __nv_bfloat16* __restrict__ Bh, int ldb, long long sB,
    int K, float alpha, const float* __restrict__ bias,
    float* __restrict__ Cf, long long sCf,
    __nv_bfloat16* __restrict__ Ch, long long sC,
    __nv_bfloat16* __restrict__ Vh, long long sV,
    const float* __restrict__ Res, long long sRes)
{
    constexpr uint32_t STAGE = 2 * 16384;

    extern __shared__ char smem[];
    const uint32_t sb = smem_u32(smem);
    const int tid = threadIdx.x, lid = tid & 31, wid = tid >> 5;
    const int bz = blockIdx.z;
    const int m0 = blockIdx.y * 128, n0 = blockIdx.x * 128;

    Ah += (long long)bz * sA;
    Bh += (long long)bz * sB;

    const int wm0 = (wid >> 2) * 64, wn0 = (wid & 3) * 32;

    // ---- loader ----
    const int l_r0 = tid >> 3, l_seg = tid & 7;
    auto load_stage = [&](int s, int kIter) {
        const uint32_t dst = sb + s * STAGE;
        const int k0 = kIter << 6;
        #pragma unroll
        for (int i = 0; i < 4; i++) {
            const int row = l_r0 + i * 32;
            const uint32_t so = row * 128 + ((l_seg ^ (row & 7)) << 4);
            cp16(dst + so,         Ah + (size_t)(m0 + row) * lda + k0 + l_seg * 8);
            cp16(dst + 16384 + so, Bh + (size_t)(n0 + row) * ldb + k0 + l_seg * 8);
        }
    };

    // ---- fragment lane constants ----
    const int matq = lid >> 3, mr = lid & 7;
    const int a_rb = ((matq & 1) << 3) + mr;
    const int a_ks = matq >> 1;
    const int b_rb = (((matq >> 1) & 1) << 3) + mr;
    const int b_ks = matq & 1;

    float acc[4][4][4];
    #pragma unroll
    for (int i = 0; i < 4; i++)
        #pragma unroll
        for (int j = 0; j < 4; j++)
            #pragma unroll
            for (int q = 0; q < 4; q++) acc[i][j][q] = 0.f;

    const int niter = K >> 6;
    load_stage(0, 0); CP_COMMIT();
    load_stage(1, 1); CP_COMMIT();
    CP_WAIT1();
    __syncthreads();

    for (int it = 0; it < niter; it++) {
        const uint32_t Ab = sb + (it & 1) * STAGE;
        #pragma unroll
        for (int ks = 0; ks < 4; ks++) {
            uint32_t ah[4][4], bh[2][4];
            #pragma unroll
            for (int mt = 0; mt < 4; mt++) {
                const int r = wm0 + mt * 16 + a_rb;
                ldm4(ah[mt], Ab + r * 128 + (((ks * 2 + a_ks) ^ (r & 7)) << 4));
            }
            #pragma unroll
            for (int g = 0; g < 2; g++) {
                const int r = wn0 + g * 16 + b_rb;
                ldm4(bh[g], Ab + 16384 + r * 128 + (((ks * 2 + b_ks) ^ (r & 7)) << 4));
            }
            #pragma unroll
            for (int mt = 0; mt < 4; mt++)
                #pragma unroll
                for (int nt = 0; nt < 4; nt++)
                    mma16816(acc[mt][nt], ah[mt], &bh[nt >> 1][(nt & 1) * 2]);
        }
        __syncthreads();
        if (it + 2 < niter) {
            load_stage(it & 1, it + 2); CP_COMMIT(); CP_WAIT1();
        } else {
            CP_COMMIT(); CP_WAIT0();
        }
        __syncthreads();
    }

    // ---------------- staged epilogue: 2 halves of 64 rows ----------------
    float* cs = reinterpret_cast<float*>(smem);
    #pragma unroll
    for (int h = 0; h < 2; h++) {
        __syncthreads();
        if ((wid >> 2) == h) {
            #pragma unroll
            for (int mt = 0; mt < 4; mt++) {
                const int rl = mt * 16 + (lid >> 2);
                #pragma unroll
                for (int nt = 0; nt < 4; nt++) {
                    const int c = wn0 + nt * 8 + ((lid & 3) << 1);
                    cs[rl * 133 + c]           = acc[mt][nt][0];
                    cs[rl * 133 + c + 1]       = acc[mt][nt][1];
                    cs[(rl + 8) * 133 + c]     = acc[mt][nt][2];
                    cs[(rl + 8) * 133 + c + 1] = acc[mt][nt][3];
                }
            }
        }
        __syncthreads();
        const int mh = m0 + h * 64;

        if (EPI == 0) {
            if (n0 < 1024) {   // q/k: [tok][1024] bf16, +bias
                const float4 bv = *reinterpret_cast<const float4*>(&bias[n0 + lid * 4]);
                __nv_bfloat16* H = Ch + (size_t)bz * sC;
                for (int rl = wid; rl < 64; rl += 8) {
                    const float* row = cs + rl * 133 + lid * 4;
                    const size_t o = (size_t)(mh + rl) * 1024 + n0 + lid * 4;
                    uint2 hi;
                    hi.x = bpack(row[0] + bv.x, row[1] + bv.y);
                    hi.y = bpack(row[2] + bv.z, row[3] + bv.w);
                    *reinterpret_cast<uint2*>(H + o) = hi;
                }
            } else {           // v: [c][tok] bf16, +bias (transposed)
                __nv_bfloat16* H = Vh + (size_t)bz * sV;
                for (int c = wid; c < 128; c += 8) {
                    const int n = n0 + c;
                    const float bvn = bias[n];
                    const float v0 = cs[(lid * 2 + 0) * 133 + c] + bvn;
                    const float v1 = cs[(lid * 2 + 1) * 133 + c] + bvn;
                    const size_t o = (size_t)(n - 1024) * HW + mh + lid * 2;
                    *reinterpret_cast<uint32_t*>(H + o) = bpack(v0, v1);
                }
            }
        } else if (EPI == 1) {  // e = exp(s*alpha) bf16 + row-sum partials
            __nv_bfloat16* E = Ch + (size_t)bz * sC;
            for (int rl = wid; rl < 64; rl += 8) {
                const float* row = cs + rl * 133 + lid * 4;
                const float e0 = __expf(row[0] * alpha);
                const float e1 = __expf(row[1] * alpha);
                const float e2 = __expf(row[2] * alpha);
                const float e3 = __expf(row[3] * alpha);
                const size_t o = (size_t)(mh + rl) * HW + n0 + lid * 4;
                uint2 hi; hi.x = bpack(e0, e1); hi.y = bpack(e2, e3);
                *reinterpret_cast<uint2*>(E + o) = hi;
                float s = (e0 + e1) + (e2 + e3);
                #pragma unroll
                for (int ofs = 16; ofs > 0; ofs >>= 1)
                    s += __shfl_xor_sync(0xffffffffu, s, ofs);
                if (lid == 0)
                    Cf[((size_t)bz * HW + mh + rl) * 32 + blockIdx.x] = s;
            }
        } else if (EPI == 2) {  // O^T: [tok][c] bf16, row-scaled by Inv
            __nv_bfloat16* H = Ch + (size_t)bz * sC;
            const float* Inv = Res + (size_t)bz * sRes;
            for (int rl = wid; rl < 64; rl += 8) {
                const float iv = Inv[mh + rl];
                const float* row = cs + rl * 133 + lid * 4;
                const size_t o = (size_t)(mh + rl) * CH + n0 + lid * 4;
                uint2 hi;
                hi.x = bpack(row[0] * iv, row[1] * iv);
                hi.y = bpack(row[2] * iv, row[3] * iv);
                *reinterpret_cast<uint2*>(H + o) = hi;
            }
        } else {                // PROJ: out[c][tok] = tile^T + bias + residual (fp32)
            const float* R = Res + (size_t)bz * sRes;
            float* C = Cf + (size_t)bz * sCf;
            for (int c = wid; c < 128; c += 8) {
                const int n = n0 + c;
                const float bvn = bias[n];
                const size_t o = (size_t)n * HW + mh + lid * 2;
                const float2 rr = *reinterpret_cast<const float2*>(R + o);
                float2 v;
                v.x = cs[(lid * 2 + 0) * 133 + c] + bvn + rr.x;
                v.y = cs[(lid * 2 + 1) * 133 + c] + bvn + rr.y;
                *reinterpret_cast<float2*>(C + o) = v;
            }
        }
    }
}

// ---------------- GroupNorm stats ----------------
__global__ __launch_bounds__(256) void gn_stats_kernel(const float* __restrict__ x)
{
    const int bg = blockIdx.x;
    const size_t base = (size_t)bg * 16 * HW;
    const int n = 16 * HW;
    float s = 0.f, ss = 0.f;
    for (int i = threadIdx.x; i < n; i += 256) {
        float v = x[base + i];
        s += v; ss += v * v;
    }
    #pragma unroll
    for (int o = 16; o > 0; o >>= 1) {
        s  += __shfl_xor_sync(0xffffffffu, s,  o);
        ss += __shfl_xor_sync(0xffffffffu, ss, o);
    }
    __shared__ float sh[16];
    const int w = threadIdx.x >> 5, l = threadIdx.x & 31;
    if (l == 0) { sh[w] = s; sh[8 + w] = ss; }
    __syncthreads();
    if (threadIdx.x == 0) {
        float S = 0.f, SS = 0.f;
        #pragma unroll
        for (int i = 0; i < 8; i++) { S += sh[i]; SS += sh[8 + i]; }
        float mean = S / (float)n;
        float var  = SS / (float)n - mean * mean;
        g_mean[bg] = mean;
        g_rstd[bg] = rsqrtf(var + EPS);
    }
}

// ---------------- normalize + transpose + bf16 ----------------
__global__ __launch_bounds__(256) void normT_kernel(
    const float* __restrict__ x, const float* __restrict__ gamma,
    const float* __restrict__ beta,
    __nv_bfloat16* __restrict__ th)
{
    __shared__ float tile[64][65];
    const int b = blockIdx.z, c0 = blockIdx.y * 64, t0 = blockIdx.x * 64;
    const int lane = threadIdx.x & 63, r0 = threadIdx.x >> 6;
    #pragma unroll
    for (int r = r0; r < 64; r += 4) {
        const int c = c0 + r;
        const int gr = b * 32 + (c >> 4);
        float v = x[((size_t)b * CH + c) * HW + t0 + lane];
        tile[r][lane] = (v - g_mean[gr]) * g_rstd[gr] * gamma[c] + beta[c];
    }
    __syncthreads();
    #pragma unroll
    for (int r = r0; r < 64; r += 4) {
        const size_t o = ((size_t)b * HW + t0 + r) * CH + c0 + lane;
        th[o] = __float2bfloat16(tile[lane][r]);
    }
}

// ---------------- weight fp32 -> bf16 ----------------
__global__ void wsplit_kernel(const float* __restrict__ in,
                              __nv_bfloat16* __restrict__ h, int n)
{
    int i = blockIdx.x * 256 + threadIdx.x;
    if (i < n) h[i] = __float2bfloat16(in[i]);
}

// ---------------- rowsum partials -> 1/sum ----------------
__global__ __launch_bounds__(256) void rowsum_inv_kernel(
    const float* __restrict__ part, float* __restrict__ inv)
{
    const int i = blockIdx.x * 256 + threadIdx.x;   // over BATCH*HW rows
    if (i < BATCH * HW) {
        const float* p = part + (size_t)i * 32;
        float s = 0.f;
        #pragma unroll
        for (int j = 0; j < 32; j++) s += p[j];
        inv[i] = 1.f / s;
    }
}

// ---------------- launch ----------------
extern "C" void kernel_launch(void* const* d_in, const int* in_sizes, int n_in,
                              void* d_out, int out_size)
{
    const float* x      = (const float*)d_in[0];
    const float* gamma  = (const float*)d_in[1];
    const float* beta   = (const float*)d_in[2];
    const float* w_qkv  = (const float*)d_in[3];
    const float* b_qkv  = (const float*)d_in[4];
    const float* w_proj = (const float*)d_in[5];
    const float* b_proj = (const float*)d_in[6];
    float* out = (float*)d_out;

    __nv_bfloat16 *xnT_h, *wqkv_h, *wproj_h, *qk_h, *v_h, *e_h, *oT_h;
    float *part, *inv;
    cudaGetSymbolAddress((void**)&xnT_h, g_xnT_h);
    cudaGetSymbolAddress((void**)&wqkv_h, g_wqkv_h);
    cudaGetSymbolAddress((void**)&wproj_h, g_wproj_h);
    cudaGetSymbolAddress((void**)&qk_h, g_qk_h);
    cudaGetSymbolAddress((void**)&v_h, g_v_h);
    cudaGetSymbolAddress((void**)&e_h, g_e);
    cudaGetSymbolAddress((void**)&part, g_part);
    cudaGetSymbolAddress((void**)&inv, g_inv);
    cudaGetSymbolAddress((void**)&oT_h, g_oT_h);

    const int SM_SO = 2 * 16384 * 2;   // 64KB (2 CTAs/SM)

    cudaFuncSetAttribute((const void*)mma_gemm_kernel<0>, cudaFuncAttributeMaxDynamicSharedMemorySize, SM_SO);
    cudaFuncSetAttribute((const void*)mma_gemm_kernel<1>, cudaFuncAttributeMaxDynamicSharedMemorySize, SM_SO);
    cudaFuncSetAttribute((const void*)mma_gemm_kernel<2>, cudaFuncAttributeMaxDynamicSharedMemorySize, SM_SO);
    cudaFuncSetAttribute((const void*)mma_gemm_kernel<3>, cudaFuncAttributeMaxDynamicSharedMemorySize, SM_SO);

    const long long sTok = (long long)HW * CH;
    const long long sQK  = (long long)HW * 1024;
    const long long sS   = (long long)HW * HW;
    const float scale2 = 1.f / sqrtf((float)CH);

    // 1) weight conversions (bf16)
    wsplit_kernel<<<(3 * CH * CH + 255) / 256, 256>>>(w_qkv, wqkv_h, 3 * CH * CH);
    wsplit_kernel<<<(CH * CH + 255) / 256, 256>>>(w_proj, wproj_h, CH * CH);

    // 2) GroupNorm stats + normalize/transpose
    gn_stats_kernel<<<BATCH * 32, 256>>>(x);
    normT_kernel<<<dim3(HW / 64, CH / 64, BATCH), 256>>>(x, gamma, beta, xnT_h);

    // 3) QKV: C[tok][oc] = xnT . w_qkv^T  (M=4096, N=1536, K=512)
    mma_gemm_kernel<0><<<dim3(12, 32, BATCH), 256, SM_SO>>>(
        xnT_h, CH, sTok, wqkv_h, CH, 0,
        CH, 1.f, b_qkv,
        nullptr, 0, qk_h, sQK, v_h, sTok, nullptr, 0);

    // 4) S-exp: e[i][j] = exp(q.k^T * scale), + row-sum partials  (M=N=4096, K=512)
    mma_gemm_kernel<1><<<dim3(32, 32, BATCH), 256, SM_SO>>>(
        qk_h, 1024, sQK, qk_h + CH, 1024, sQK,
        CH, scale2, nullptr,
        part, 0, e_h, sS, nullptr, 0, nullptr, 0);

    // 5) rowsum partials -> inverse
    rowsum_inv_kernel<<<(BATCH * HW + 255) / 256, 256>>>(part, inv);

    // 6) O: O^T[tok][c] = (e . v^T) * inv[tok]  (M=4096, N=512, K=4096)
    mma_gemm_kernel<2><<<dim3(4, 32, BATCH), 256, SM_SO>>>(
        e_h, HW, sS, v_h, HW, sTok,
        HW, 1.f, nullptr,
        nullptr, 0, oT_h, sTok, nullptr, 0, inv, (long long)HW);

    // 7) PROJ: out[c][tok] = oT . w_proj^T + b_proj + x  (M=4096, N=512, K=512)
    mma_gemm_kernel<3><<<dim3(4, 32, BATCH), 256, SM_SO>>>(
        oT_h, CH, sTok, wproj_h, CH, 0,
        CH, 1.f, b_proj,
        out, sTok, nullptr, 0, nullptr, 0, x, sTok);
}